// round 1
// baseline (speedup 1.0000x reference)
#include <cuda_runtime.h>

#define B_TOTAL 65536
#define H 50
#define L_LAYERS 6
#define IN_SZ 3
#define T_SEQ 3
#define G 200            // 4*H gates
#define TB 64            // batch tile per CTA
#define NTH 400          // 8 b-groups x 50 units

typedef unsigned long long u64;

// ---- packed f32x2 helpers (sm_103a dual-fp32 pipe) ----
static __device__ __forceinline__ u64 ffma2(u64 a, u64 b, u64 c) {
    u64 d;
    asm("fma.rn.f32x2 %0, %1, %2, %3;" : "=l"(d) : "l"(a), "l"(b), "l"(c));
    return d;
}
static __device__ __forceinline__ u64 pack2(float lo, float hi) {
    return (u64)__float_as_uint(lo) | ((u64)__float_as_uint(hi) << 32);
}
static __device__ __forceinline__ float lo32(u64 v) { return __uint_as_float((unsigned)v); }
static __device__ __forceinline__ float hi32(u64 v) { return __uint_as_float((unsigned)(v >> 32)); }

static __device__ __forceinline__ float sigf(float x) {
    float e = __expf(-x);
    return __fdividef(1.0f, 1.0f + e);
}
static __device__ __forceinline__ float tanh_fast(float x) {
    x = fminf(fmaxf(x, -15.0f), 15.0f);
    float e = __expf(-2.0f * x);
    return (1.0f - e) * __fdividef(1.0f, 1.0f + e);
}

// GEMM partial: acc[m][e*4+g] += A-pairs * W-pairs along K (packed in f32x2)
// A: [kcount][64] u64 (k-pairs x batch), W: [kcount][200] u64 (k-pairs x gates, gate-interleaved)
static __device__ __forceinline__ void gemm_acc(
    const u64* __restrict__ A, const u64* __restrict__ W,
    int kcount, int bg, int gg, u64 acc[4][8])
{
    const u64* Ab = A + 2 * bg;     // chunks at +0,+16,+32,+48 (conflict-free LDS.128 across bg)
    const u64* Wb = W + 4 * gg;
    #pragma unroll 5
    for (int kp = 0; kp < kcount; ++kp) {
        ulonglong2 a0 = *(const ulonglong2*)(Ab + 0);
        ulonglong2 a1 = *(const ulonglong2*)(Ab + 16);
        ulonglong2 a2 = *(const ulonglong2*)(Ab + 32);
        ulonglong2 a3 = *(const ulonglong2*)(Ab + 48);
        ulonglong2 w0 = *(const ulonglong2*)(Wb + 0);
        ulonglong2 w1 = *(const ulonglong2*)(Wb + 2);
        u64 av[8] = {a0.x, a0.y, a1.x, a1.y, a2.x, a2.y, a3.x, a3.y};
        u64 wv[4] = {w0.x, w0.y, w1.x, w1.y};
        #pragma unroll
        for (int m = 0; m < 4; ++m)
            #pragma unroll
            for (int e = 0; e < 2; ++e)
                #pragma unroll
                for (int g = 0; g < 4; ++g)
                    acc[m][e * 4 + g] = ffma2(av[m * 2 + e], wv[g], acc[m][e * 4 + g]);
        Ab += 64;
        Wb += 200;
    }
}

// smem layout (u64 units):
//  Wp  [50][200]   : 10000   combined (w_ih | w_hh) k-paired, gate-interleaved
//  ys2 [3][25][64] :  4800   per-timestep layer outputs, k-paired
//  hb2 [25][64]    :  1600   recurrent h, k-paired
//  xs2 [3][2][64]  :   384   layer-0 inputs, k-paired (k=3 padded to 4)
//  then floats: c_s[50][64]=3200, bias_s[200], fcw_s[50]
#define SMEM_U64   (10000 + 4800 + 1600 + 384)
#define SMEM_BYTES (SMEM_U64 * 8 + (3200 + 200 + 56) * 4)

__global__ void __launch_bounds__(NTH, 1) lstm_kernel(
    const float* __restrict__ x,     const float* __restrict__ h0,
    const float* __restrict__ c0,    const float* __restrict__ w_ih0,
    const float* __restrict__ w_ih,  const float* __restrict__ w_hh,
    const float* __restrict__ b_ih,  const float* __restrict__ b_hh,
    const float* __restrict__ fc_w,  const float* __restrict__ fc_b,
    float* __restrict__ out)
{
    extern __shared__ u64 smem[];
    u64* Wp    = smem;
    u64* ys2   = smem + 10000;
    u64* hb2   = smem + 14800;
    u64* xs2   = smem + 16400;
    float* c_s    = (float*)(smem + SMEM_U64);
    float* bias_s = c_s + 3200;
    float* fcw_s  = bias_s + 200;

    const int tid  = threadIdx.x;
    const int bg   = tid & 7;    // batch group (owns b = 2bg+e+16m)
    const int gg   = tid >> 3;   // hidden unit 0..49 (owns gates i,f,g,o of this unit)
    const int boff = blockIdx.x * TB;

    // layer-0 input staging: xs2[t][kp][b], kp0={x0,x1}, kp1={x2,0}
    for (int idx = tid; idx < 6 * 64; idx += NTH) {
        int b = idx & 63; int r = idx >> 6; int t = r % 3; int kp = r / 3;
        const float* xb = x + (size_t)(boff + b) * (IN_SZ * T_SEQ) + t;
        xs2[(t * 2 + kp) * 64 + b] = (kp == 0) ? pack2(xb[0], xb[3]) : pack2(xb[6], 0.0f);
    }
    if (tid < H) fcw_s[tid] = fc_w[tid];

    const u64* h0d = (const u64*)h0;   // H=50 even -> 25 u64 per row

    for (int l = 0; l < L_LAYERS; ++l) {
        const int kx = (l == 0) ? 2 : 25;   // input-part k-pairs
        // --- fill weights (gate-interleaved: gp = unit*4 + type; row r = type*50+unit) ---
        const int nW = (kx + 25) * 200;
        for (int idx = tid; idx < nW; idx += NTH) {
            int gp = idx % 200; int kp = idx / 200;
            int unit = gp >> 2, type = gp & 3; int r = type * H + unit;
            u64 v;
            if (l == 0) {
                if (kp == 0)      v = pack2(w_ih0[r * 3 + 0], w_ih0[r * 3 + 1]);
                else if (kp == 1) v = pack2(w_ih0[r * 3 + 2], 0.0f);
                else { const float* w = w_hh + (size_t)r * H + (kp - 2) * 2; v = pack2(w[0], w[1]); }
            } else {
                if (kp < 25) { const float* w = w_ih + ((size_t)(l - 1) * G + r) * H + kp * 2;        v = pack2(w[0], w[1]); }
                else         { const float* w = w_hh + ((size_t)l       * G + r) * H + (kp - 25) * 2; v = pack2(w[0], w[1]); }
            }
            Wp[kp * 200 + gp] = v;
        }
        for (int idx = tid; idx < 200; idx += NTH) {
            int unit = idx >> 2, type = idx & 3; int r = type * H + unit;
            bias_s[idx] = b_ih[l * G + r] + b_hh[l * G + r];
        }
        for (int idx = tid; idx < 25 * 64; idx += NTH) {
            int kp = idx % 25; int b = idx / 25;
            hb2[kp * 64 + b] = h0d[((size_t)l * B_TOTAL + boff + b) * 25 + kp];
        }
        for (int idx = tid; idx < 50 * 64; idx += NTH) {
            int u = idx % 50; int b = idx / 50;
            c_s[u * 64 + b] = c0[((size_t)l * B_TOTAL + boff + b) * 50 + u];
        }
        __syncthreads();

        float bvals[4];
        #pragma unroll
        for (int j = 0; j < 4; ++j) bvals[j] = bias_s[gg * 4 + j];

        for (int t = 0; t < T_SEQ; ++t) {
            u64 acc[4][8];
            #pragma unroll
            for (int m = 0; m < 4; ++m)
                #pragma unroll
                for (int j = 0; j < 8; ++j)
                    acc[m][j] = pack2(bvals[j & 3], 0.0f);

            const u64* A1 = (l == 0) ? (xs2 + t * 2 * 64) : (ys2 + t * 25 * 64);
            gemm_acc(A1, Wp, kx, bg, gg, acc);          // input part
            gemm_acc(hb2, Wp + kx * 200, 25, bg, gg, acc); // recurrent part
            __syncthreads();   // all reads of ys2[t]/hb2 done before overwrite

            float* ysf = (float*)(ys2 + t * 25 * 64);
            float* hbf = (float*)hb2;
            #pragma unroll
            for (int m = 0; m < 4; ++m) {
                #pragma unroll
                for (int e = 0; e < 2; ++e) {
                    int b = 2 * bg + 16 * m + e;
                    float gi = lo32(acc[m][e * 4 + 0]) + hi32(acc[m][e * 4 + 0]);
                    float gf = lo32(acc[m][e * 4 + 1]) + hi32(acc[m][e * 4 + 1]);
                    float gc = lo32(acc[m][e * 4 + 2]) + hi32(acc[m][e * 4 + 2]);
                    float go = lo32(acc[m][e * 4 + 3]) + hi32(acc[m][e * 4 + 3]);
                    float ii = sigf(gi), ff = sigf(gf);
                    float gt = tanh_fast(gc), oo = sigf(go);
                    float cn = ff * c_s[gg * 64 + b] + ii * gt;
                    c_s[gg * 64 + b] = cn;
                    float hn = oo * tanh_fast(cn);
                    int fidx = ((gg >> 1) * 64 + b) * 2 + (gg & 1);  // k-paired store
                    ysf[fidx] = hn;
                    hbf[fidx] = hn;
                }
            }
            __syncthreads();
        }
    }

    // FC: out[b] = ys[T-1][b] . fc_w + fc_b
    if (tid < TB) {
        const float2* hl = (const float2*)(ys2 + 2 * 25 * 64);
        float s = fc_b[0];
        #pragma unroll
        for (int kp = 0; kp < 25; ++kp) {
            float2 h2 = hl[kp * 64 + tid];
            s += h2.x * fcw_s[2 * kp] + h2.y * fcw_s[2 * kp + 1];
        }
        out[boff + tid] = s;
    }
}

extern "C" void kernel_launch(void* const* d_in, const int* in_sizes, int n_in,
                              void* d_out, int out_size) {
    const float* x     = (const float*)d_in[0];
    const float* h0    = (const float*)d_in[1];
    const float* c0    = (const float*)d_in[2];
    const float* w_ih0 = (const float*)d_in[3];
    const float* w_ih  = (const float*)d_in[4];
    const float* w_hh  = (const float*)d_in[5];
    const float* b_ih  = (const float*)d_in[6];
    const float* b_hh  = (const float*)d_in[7];
    const float* fc_w  = (const float*)d_in[8];
    const float* fc_b  = (const float*)d_in[9];
    float* out = (float*)d_out;

    cudaFuncSetAttribute(lstm_kernel, cudaFuncAttributeMaxDynamicSharedMemorySize, SMEM_BYTES);
    lstm_kernel<<<B_TOTAL / TB, NTH, SMEM_BYTES>>>(
        x, h0, c0, w_ih0, w_ih, w_hh, b_ih, b_hh, fc_w, fc_b, out);
}

// round 3
// speedup vs baseline: 1.5632x; 1.5632x over previous
#include <cuda_runtime.h>
#include <cuda_fp16.h>

#define BTOT     65536
#define ROWS_CTA 128
#define NCTA     (BTOT / ROWS_CTA)   // 512
#define NTH      256                 // 8 warps, 16 rows each
#define L_LAYERS 6
#define KT       7                   // 7 k16-tiles: cols [0..49 input][50..99 h][100..111 pad]
#define ASTR     224                 // row stride bytes (112 fp16)

// smem offsets (bytes)
#define B_OFF    0
#define BSEG     44800               // 200 rows * 224
#define A_OFF    89600
#define ASEG     3584                // 16 rows * 224
#define AW_BYTES 7168                // hi+lo per warp
#define YS_OFF   146944              // 8 warps * 9600
#define YW_BYTES 9600                // 3 t * 16 rows * 50 units * 4B
#define BIAS_OFF 223744              // 50 float4
#define FCW_OFF  224544              // 50 floats
#define SMEM_BYTES 224768

typedef unsigned u32;

__device__ __align__(16) char  g_wB[L_LAYERS * 89600];  // [l][seg(hi,lo)][n=200][k=112] fp16
__device__ float               g_bias[L_LAYERS * 200];  // [l][unit][gate i,f,g,o]

static __device__ __forceinline__ u32 smem_u32(const void* p) {
    u32 a;
    asm("{ .reg .u64 t; cvta.to.shared.u64 t, %1; cvt.u32.u64 %0, t; }" : "=r"(a) : "l"(p));
    return a;
}
static __device__ __forceinline__ void ldsm4(u32 addr, u32* r) {
    asm volatile("ldmatrix.sync.aligned.m8n8.x4.shared.b16 {%0,%1,%2,%3}, [%4];"
                 : "=r"(r[0]), "=r"(r[1]), "=r"(r[2]), "=r"(r[3]) : "r"(addr));
}
static __device__ __forceinline__ uint2 ldsm2(u32 addr) {
    uint2 v;
    asm volatile("ldmatrix.sync.aligned.m8n8.x2.shared.b16 {%0,%1}, [%2];"
                 : "=r"(v.x), "=r"(v.y) : "r"(addr));
    return v;
}
static __device__ __forceinline__ void mma4(float& c0, float& c1, float& c2, float& c3,
                                            const u32* a, uint2 b) {
    asm("mma.sync.aligned.m16n8k16.row.col.f32.f16.f16.f32 "
        "{%0,%1,%2,%3},{%4,%5,%6,%7},{%8,%9},{%0,%1,%2,%3};"
        : "+f"(c0), "+f"(c1), "+f"(c2), "+f"(c3)
        : "r"(a[0]), "r"(a[1]), "r"(a[2]), "r"(a[3]), "r"(b.x), "r"(b.y));
}
static __device__ __forceinline__ float sigf(float x) {
    float e = __expf(-x);
    return __fdividef(1.0f, 1.0f + e);
}
static __device__ __forceinline__ float tanh_fast(float x) {
    x = fminf(fmaxf(x, -15.0f), 15.0f);
    float e = __expf(-2.0f * x);
    return (1.0f - e) * __fdividef(1.0f, 1.0f + e);
}
static __device__ __forceinline__ void split16(float v, __half& hi, __half& lo) {
    hi = __float2half_rn(v);
    lo = __float2half_rn(v - __half2float(hi));
}

// ---------------- prep: pack weights (fp16 hi/lo, gate-interleaved) + bias ----------------
__global__ void prep_kernel(const float* __restrict__ w_ih0, const float* __restrict__ w_ih,
                            const float* __restrict__ w_hh,  const float* __restrict__ b_ih,
                            const float* __restrict__ b_hh) {
    int idx = blockIdx.x * 256 + threadIdx.x;
    if (idx >= L_LAYERS * 200 * 112) return;
    int k = idx % 112;
    int n = (idx / 112) % 200;
    int l = idx / (112 * 200);
    int u = n >> 2, g = n & 3, rt = g * 50 + u;   // torch row (gate blocks of 50)
    float wv = 0.0f;
    if (k < 50)       wv = (l == 0) ? (k < 3 ? w_ih0[rt * 3 + k] : 0.0f)
                                    : w_ih[((size_t)(l - 1) * 200 + rt) * 50 + k];
    else if (k < 100) wv = w_hh[((size_t)l * 200 + rt) * 50 + (k - 50)];
    __half hh, hl; split16(wv, hh, hl);
    __half* base = (__half*)g_wB;
    base[((size_t)(l * 2 + 0) * 200 + n) * 112 + k] = hh;
    base[((size_t)(l * 2 + 1) * 200 + n) * 112 + k] = hl;
    if (k == 0) g_bias[l * 200 + u * 4 + g] = b_ih[l * 200 + rt] + b_hh[l * 200 + rt];
}

// ---------------- main: 8 independent 16-row warps, HMMA fp16-split ----------------
__global__ void __launch_bounds__(NTH, 1) lstm_hmma_kernel(
    const float* __restrict__ x,    const float* __restrict__ h0,
    const float* __restrict__ c0,   const float* __restrict__ fc_w,
    const float* __restrict__ fc_b, float* __restrict__ out)
{
    extern __shared__ char smem[];
    const u32 sbase = smem_u32(smem);
    const int tid = threadIdx.x, lane = tid & 31, w = tid >> 5;
    const int q = lane & 3, r4 = lane >> 2, p = q >> 1;
    const int row_e = r4 + 8 * (q & 1);                // epilogue-owned row in warp tile
    const int boff = blockIdx.x * ROWS_CTA;
    const int grow = boff + w * 16 + row_e;            // global batch row

    // zero A (covers pad cols 100..111 and layer-0 cols 3..49 forever)
    for (int i = tid; i < 57344 / 16; i += NTH)
        ((float4*)(smem + A_OFF))[i] = make_float4(0.f, 0.f, 0.f, 0.f);
    if (tid < 50) ((float*)(smem + FCW_OFF))[tid] = fc_w[tid];

    char* Ah = smem + A_OFF + w * AW_BYTES;
    char* Al = Ah + ASEG;
    const u32 aB = sbase + A_OFF + w * AW_BYTES + (lane & 15) * ASTR + (lane >> 4) * 16;
    const u32 bB = sbase + B_OFF + (lane & 7) * ASTR + ((lane >> 3) & 1) * 16;
    u32* ysw = (u32*)(smem + YS_OFF + w * YW_BYTES);

    // cache x for own row (lanes 0..15)
    float xc[9];
    if (lane < 16) {
        const float* xp = x + (size_t)(boff + w * 16 + lane) * 9;
        #pragma unroll
        for (int i = 0; i < 9; ++i) xc[i] = xp[i];
    }

    float c[25];

    #pragma unroll 1
    for (int l = 0; l < L_LAYERS; ++l) {
        __syncthreads();                                   // prev layer's B/ys fully consumed
        const float4* wsrc = (const float4*)g_wB + (size_t)l * 5600;
        for (int i = tid; i < 5600; i += NTH)
            ((float4*)(smem + B_OFF))[i] = __ldg(wsrc + i);
        for (int i = tid; i < 200; i += NTH)
            ((float*)(smem + BIAS_OFF))[i] = g_bias[l * 200 + i];
        __syncthreads();

        // stage h0 (split fp16 into A cols 50..99) + load c0 into regs
        {
            const float* hp = h0 + ((size_t)l * BTOT + grow) * 50;
            const float* cp = c0 + ((size_t)l * BTOT + grow) * 50;
            #pragma unroll
            for (int n = 0; n < 25; ++n) {
                int u = 2 * n + p;
                c[n] = cp[u];
                __half hh, hl; split16(hp[u], hh, hl);
                *(__half*)(Ah + row_e * ASTR + (50 + u) * 2) = hh;
                *(__half*)(Al + row_e * ASTR + (50 + u) * 2) = hl;
            }
        }

        #pragma unroll 1
        for (int t = 0; t < 3; ++t) {
            // stage input cols 0..49
            if (l == 0) {
                if (lane < 16) {
                    #pragma unroll
                    for (int i = 0; i < 3; ++i) {
                        __half hh, hl; split16(xc[i * 3 + t], hh, hl);
                        *(__half*)(Ah + lane * ASTR + i * 2) = hh;
                        *(__half*)(Al + lane * ASTR + i * 2) = hl;
                    }
                }
            } else {
                const int row = lane & 15;
                #pragma unroll
                for (int u = lane >> 4; u < 50; u += 2) {
                    u32 y = ysw[t * 800 + row * 50 + u];
                    *(unsigned short*)(Ah + row * ASTR + u * 2) = (unsigned short)y;
                    *(unsigned short*)(Al + row * ASTR + u * 2) = (unsigned short)(y >> 16);
                }
            }
            __syncwarp();

            // load all A fragments for this step
            u32 a[2][KT][4];
            #pragma unroll
            for (int seg = 0; seg < 2; ++seg)
                #pragma unroll
                for (int kt = 0; kt < KT; ++kt)
                    ldsm4(aB + seg * ASEG + kt * 32, a[seg][kt]);

            float fcacc = 0.0f;
            const bool last = (l == L_LAYERS - 1) && (t == 2);

            #pragma unroll
            for (int n = 0; n < 25; ++n) {
                float cc0 = 0.f, cc1 = 0.f, cc2 = 0.f, cc3 = 0.f;
                const u32 bn = bB + n * 1792;
                #pragma unroll
                for (int kt = 0; kt < KT; ++kt) {
                    uint2 bh = ldsm2(bn + kt * 32);
                    mma4(cc0, cc1, cc2, cc3, a[0][kt], bh);   // Ah*Wh
                    mma4(cc0, cc1, cc2, cc3, a[1][kt], bh);   // Al*Wh
                    uint2 bl = ldsm2(bn + BSEG + kt * 32);
                    mma4(cc0, cc1, cc2, cc3, a[0][kt], bl);   // Ah*Wl
                }
                // gate exchange: (q even has i,f row r4; q odd has g,o row r4+8 after swap)
                float sa = (q & 1) ? cc0 : cc2; sa = __shfl_xor_sync(0xffffffffu, sa, 1);
                float sb = (q & 1) ? cc1 : cc3; sb = __shfl_xor_sync(0xffffffffu, sb, 1);
                float gi, gf, gg, go;
                if (q & 1) { gi = sa;  gf = sb;  gg = cc2; go = cc3; }
                else       { gi = cc0; gf = cc1; gg = sa;  go = sb;  }
                const int u = 2 * n + p;
                float4 bs = ((const float4*)(smem + BIAS_OFF))[u];
                gi += bs.x; gf += bs.y; gg += bs.z; go += bs.w;
                float cn = sigf(gf) * c[n] + sigf(gi) * tanh_fast(gg);
                c[n] = cn;
                float hv = sigf(go) * tanh_fast(cn);
                if (last) {
                    fcacc += hv * ((const float*)(smem + FCW_OFF))[u];
                } else {
                    __half hh, hl; split16(hv, hh, hl);
                    if (t < 2) {
                        *(__half*)(Ah + row_e * ASTR + (50 + u) * 2) = hh;
                        *(__half*)(Al + row_e * ASTR + (50 + u) * 2) = hl;
                    }
                    if (l < L_LAYERS - 1) {
                        u32 pk = (u32)__half_as_ushort(hh) | ((u32)__half_as_ushort(hl) << 16);
                        ysw[t * 800 + row_e * 50 + u] = pk;
                    }
                }
            }
            if (last) {
                fcacc += __shfl_xor_sync(0xffffffffu, fcacc, 2);  // even/odd unit halves
                if (q < 2) out[grow] = fcacc + fc_b[0];
            }
        }
    }
}

extern "C" void kernel_launch(void* const* d_in, const int* in_sizes, int n_in,
                              void* d_out, int out_size) {
    const float* x     = (const float*)d_in[0];
    const float* h0    = (const float*)d_in[1];
    const float* c0    = (const float*)d_in[2];
    const float* w_ih0 = (const float*)d_in[3];
    const float* w_ih  = (const float*)d_in[4];
    const float* w_hh  = (const float*)d_in[5];
    const float* b_ih  = (const float*)d_in[6];
    const float* b_hh  = (const float*)d_in[7];
    const float* fc_w  = (const float*)d_in[8];
    const float* fc_b  = (const float*)d_in[9];
    float* out = (float*)d_out;

    prep_kernel<<<(L_LAYERS * 200 * 112 + 255) / 256, 256>>>(w_ih0, w_ih, w_hh, b_ih, b_hh);

    static int once = 0;
    if (!once) {
        cudaFuncSetAttribute(lstm_hmma_kernel,
                             cudaFuncAttributeMaxDynamicSharedMemorySize, SMEM_BYTES);
        once = 1;
    }
    lstm_hmma_kernel<<<NCTA, NTH, SMEM_BYTES>>>(x, h0, c0, fc_w, fc_b, out);
}

// round 4
// speedup vs baseline: 1.7029x; 1.0894x over previous
#include <cuda_runtime.h>
#include <cuda_fp16.h>

#define BTOT     65536
#define ROWS_CTA 256
#define NCTA     (BTOT / ROWS_CTA)   // 256
#define NTH      256                 // 8 warps x 32 rows
#define L_LAYERS 6
#define KT       7                   // k16 tiles over cols [0..49 in][50..99 h][100 bias1][101..111 pad]
#define ASTR     240                 // row stride bytes (conflict-free: 60r mod 32 distinct)

// smem (bytes): B [seg][n=200][120 cols] then A [warp][seg][32 rows][120 cols] then fcw
#define BSEG     48000               // 200 * 240
#define A_OFF    96000
#define A_SEG    7680                // 32 * 240
#define AW_BYTES 15360               // hi+lo
#define FCW_OFF  218880
#define SMEM_BYTES 219136

typedef unsigned u32;

__device__ __align__(16) char g_wB[L_LAYERS * 96000];     // packed fp16 weights+bias, 240B rows
__device__ u32                g_ys[3ull * BTOT * 50];     // packed (hi,lo) hidden outputs

static __device__ __forceinline__ u32 smem_u32(const void* p) {
    u32 a;
    asm("{ .reg .u64 t; cvta.to.shared.u64 t, %1; cvt.u32.u64 %0, t; }" : "=r"(a) : "l"(p));
    return a;
}
static __device__ __forceinline__ void ldsm4(u32 addr, u32* r) {
    asm volatile("ldmatrix.sync.aligned.m8n8.x4.shared.b16 {%0,%1,%2,%3}, [%4];"
                 : "=r"(r[0]), "=r"(r[1]), "=r"(r[2]), "=r"(r[3]) : "r"(addr));
}
static __device__ __forceinline__ void ldsm2(u32 addr, u32* r) {
    asm volatile("ldmatrix.sync.aligned.m8n8.x2.shared.b16 {%0,%1}, [%2];"
                 : "=r"(r[0]), "=r"(r[1]) : "r"(addr));
}
static __device__ __forceinline__ void mma4(float* c, const u32* a, u32 b0, u32 b1) {
    asm("mma.sync.aligned.m16n8k16.row.col.f32.f16.f16.f32 "
        "{%0,%1,%2,%3},{%4,%5,%6,%7},{%8,%9},{%0,%1,%2,%3};"
        : "+f"(c[0]), "+f"(c[1]), "+f"(c[2]), "+f"(c[3])
        : "r"(a[0]), "r"(a[1]), "r"(a[2]), "r"(a[3]), "r"(b0), "r"(b1));
}
static __device__ __forceinline__ float rcpa(float x) {
    float r; asm("rcp.approx.f32 %0, %1;" : "=f"(r) : "f"(x)); return r;
}
static __device__ __forceinline__ void split16(float v, __half& hi, __half& lo) {
    hi = __float2half_rn(v);
    lo = __float2half_rn(v - __half2float(hi));
}
// fused LSTM cell update: returns h, updates c in-place. bias already in gates via MMA.
static __device__ __forceinline__ float lstm_cell(float a0, float a1, float a2, float a3,
                                                  int qodd, float& cst) {
    float sa = qodd ? a0 : a2; sa = __shfl_xor_sync(0xffffffffu, sa, 1);
    float sb = qodd ? a1 : a3; sb = __shfl_xor_sync(0xffffffffu, sb, 1);
    float gi, gf, gg, go;
    if (qodd) { gi = sa; gf = sb; gg = a2; go = a3; }
    else      { gi = a0; gf = a1; gg = sa; go = sb; }
    float e1 = __expf(-gi);
    float ef = __expf(-gf);
    float g2 = fminf(fmaxf(gg, -15.f), 15.f);
    float e2 = __expf(-2.f * g2);
    float cn = cst * rcpa(1.f + ef) + (1.f - e2) * rcpa((1.f + e1) * (1.f + e2));
    cst = cn;
    float cc = fminf(fmaxf(cn, -15.f), 15.f);
    float ec = __expf(-2.f * cc);
    float eo = __expf(-go);
    return (1.f - ec) * rcpa((1.f + eo) * (1.f + ec));
}

// ---------------- prep: weights + bias -> fp16 hi/lo, gate-interleaved, 240B rows ----------------
__global__ void prep_kernel(const float* __restrict__ w_ih0, const float* __restrict__ w_ih,
                            const float* __restrict__ w_hh,  const float* __restrict__ b_ih,
                            const float* __restrict__ b_hh) {
    int idx = blockIdx.x * 256 + threadIdx.x;
    if (idx >= L_LAYERS * 200 * 120) return;
    int k = idx % 120;
    int n = (idx / 120) % 200;
    int l = idx / (120 * 200);
    int u = n >> 2, g = n & 3, rt = g * 50 + u;
    float wv = 0.0f;
    if (k < 50)        wv = (l == 0) ? (k < 3 ? w_ih0[rt * 3 + k] : 0.0f)
                                     : w_ih[((size_t)(l - 1) * 200 + rt) * 50 + k];
    else if (k < 100)  wv = w_hh[((size_t)l * 200 + rt) * 50 + (k - 50)];
    else if (k == 100) wv = b_ih[l * 200 + rt] + b_hh[l * 200 + rt];
    __half hh, hl; split16(wv, hh, hl);
    __half* base = (__half*)(g_wB + (size_t)l * 96000);
    base[(size_t)n * 120 + k]              = hh;
    base[(size_t)(200 + n) * 120 + k]      = hl;
}

// ---------------- main ----------------
__global__ void __launch_bounds__(NTH, 1) lstm_hmma_kernel(
    const float* __restrict__ x,    const float* __restrict__ h0,
    const float* __restrict__ c0,   const float* __restrict__ fc_w,
    const float* __restrict__ fc_b, float* __restrict__ out)
{
    extern __shared__ char smem[];
    const u32 sbase = smem_u32(smem);
    const int tid = threadIdx.x, lane = tid & 31, w = tid >> 5;
    const int q = lane & 3, r4 = lane >> 2, p = q >> 1, qodd = q & 1;
    const int row_e = r4 + 8 * qodd;
    const int wrb = blockIdx.x * ROWS_CTA + w * 32;
    const int grow0 = wrb + row_e, grow1 = grow0 + 16;
    float* fcw_s = (float*)(smem + FCW_OFF);
    char* Awarp = smem + A_OFF + w * AW_BYTES;

    for (int i = tid; i < (8 * AW_BYTES) / 16; i += NTH)
        ((float4*)(smem + A_OFF))[i] = make_float4(0.f, 0.f, 0.f, 0.f);
    if (tid < 50) fcw_s[tid] = fc_w[tid];
    __syncthreads();
    *(__half*)(Awarp + lane * ASTR + 200) = __float2half(1.0f);   // bias column k=100

    const u32 aB  = sbase + A_OFF + w * AW_BYTES + (lane & 15) * ASTR + (lane >> 4) * 16;
    const u32 bB4 = sbase + (lane & 7) * ASTR + ((lane >> 3) & 1) * 16
                          + ((lane >> 4) & 1) * (8 * ASTR);

    float c0r[25], c1r[25];
    float fc0 = 0.f, fc1 = 0.f;
    u32 afr[2][2][KT][4];

    #pragma unroll 1
    for (int l = 0; l < L_LAYERS; ++l) {
        __syncthreads();
        const float4* ws = (const float4*)(g_wB + (size_t)l * 96000);
        for (int i = tid; i < 6000; i += NTH) ((float4*)smem)[i] = __ldg(ws + i);
        __syncthreads();

        {   // h0 staging (row = lane), c0 -> regs
            const float2* hp = (const float2*)(h0 + ((size_t)l * BTOT + wrb + lane) * 50);
            char* Ar = Awarp + lane * ASTR;
            #pragma unroll
            for (int i = 0; i < 25; ++i) {
                float2 v = hp[i];
                __half ah, al, bh, bl; split16(v.x, ah, al); split16(v.y, bh, bl);
                *(__half2*)(Ar + (50 + 2 * i) * 2)         = __halves2half2(ah, bh);
                *(__half2*)(Ar + A_SEG + (50 + 2 * i) * 2) = __halves2half2(al, bl);
            }
            const float* cp = c0 + (size_t)l * BTOT * 50;
            #pragma unroll
            for (int un = 0; un < 25; ++un) {
                c0r[un] = cp[(size_t)grow0 * 50 + 2 * un + p];
                c1r[un] = cp[(size_t)grow1 * 50 + 2 * un + p];
            }
        }

        #pragma unroll 1
        for (int t = 0; t < 3; ++t) {
            char* Ar = Awarp + lane * ASTR;
            if (l == 0) {
                const float* xp = x + (size_t)(wrb + lane) * 9 + t;
                __half a0, b0, a1, b1, a2, b2;
                split16(xp[0], a0, b0); split16(xp[3], a1, b1); split16(xp[6], a2, b2);
                *(__half2*)(Ar)             = __halves2half2(a0, a1);
                *(__half*)(Ar + 4)          = a2;
                *(__half2*)(Ar + A_SEG)     = __halves2half2(b0, b1);
                *(__half*)(Ar + A_SEG + 4)  = b2;
            } else {
                const u32* yp = g_ys + ((size_t)t * BTOT + wrb + lane) * 50;
                #pragma unroll
                for (int i = 0; i < 25; ++i) {
                    u32 y0 = yp[2 * i], y1 = yp[2 * i + 1];
                    *(__half2*)(Ar + 4 * i) = __halves2half2(
                        __ushort_as_half((unsigned short)y0), __ushort_as_half((unsigned short)y1));
                    *(__half2*)(Ar + A_SEG + 4 * i) = __halves2half2(
                        __ushort_as_half((unsigned short)(y0 >> 16)),
                        __ushort_as_half((unsigned short)(y1 >> 16)));
                }
            }
            __syncwarp();

            #pragma unroll
            for (int seg = 0; seg < 2; ++seg)
                #pragma unroll
                for (int mt = 0; mt < 2; ++mt)
                    #pragma unroll
                    for (int kt = 0; kt < KT; ++kt)
                        ldsm4(aB + seg * A_SEG + mt * (16 * ASTR) + kt * 32, afr[seg][mt][kt]);

            const bool last = (l == L_LAYERS - 1) && (t == 2);

            #pragma unroll
            for (int j = 0; j < 13; ++j) {
                const u32 tb = bB4 + j * (16 * ASTR);
                float A00[4] = {0.f,0.f,0.f,0.f}, A01[4] = {0.f,0.f,0.f,0.f};
                float A10[4] = {0.f,0.f,0.f,0.f}, A11[4] = {0.f,0.f,0.f,0.f};
                if (j < 12) {
                    #pragma unroll
                    for (int kt = 0; kt < KT; ++kt) {
                        u32 bh[4], bl[4];
                        ldsm4(tb + kt * 32, bh);
                        ldsm4(tb + BSEG + kt * 32, bl);
                        mma4(A00, afr[0][0][kt], bh[0], bh[1]);
                        mma4(A00, afr[1][0][kt], bh[0], bh[1]);
                        mma4(A00, afr[0][0][kt], bl[0], bl[1]);
                        mma4(A01, afr[0][0][kt], bh[2], bh[3]);
                        mma4(A01, afr[1][0][kt], bh[2], bh[3]);
                        mma4(A01, afr[0][0][kt], bl[2], bl[3]);
                        mma4(A10, afr[0][1][kt], bh[0], bh[1]);
                        mma4(A10, afr[1][1][kt], bh[0], bh[1]);
                        mma4(A10, afr[0][1][kt], bl[0], bl[1]);
                        mma4(A11, afr[0][1][kt], bh[2], bh[3]);
                        mma4(A11, afr[1][1][kt], bh[2], bh[3]);
                        mma4(A11, afr[0][1][kt], bl[2], bl[3]);
                    }
                } else {
                    #pragma unroll
                    for (int kt = 0; kt < KT; ++kt) {
                        u32 bh[2], bl[2];
                        ldsm2(tb + kt * 32, bh);
                        ldsm2(tb + BSEG + kt * 32, bl);
                        mma4(A00, afr[0][0][kt], bh[0], bh[1]);
                        mma4(A00, afr[1][0][kt], bh[0], bh[1]);
                        mma4(A00, afr[0][0][kt], bl[0], bl[1]);
                        mma4(A10, afr[0][1][kt], bh[0], bh[1]);
                        mma4(A10, afr[1][1][kt], bh[0], bh[1]);
                        mma4(A10, afr[0][1][kt], bl[0], bl[1]);
                    }
                }
                const int nmax = (j < 12) ? 2 : 1;
                #pragma unroll
                for (int nn = 0; nn < nmax; ++nn) {
                    const int un = 2 * j + nn;
                    const int u = 2 * un + p;
                    const float* P0 = nn ? A01 : A00;
                    const float* P1 = nn ? A11 : A10;
                    float hv0 = lstm_cell(P0[0], P0[1], P0[2], P0[3], qodd, c0r[un]);
                    float hv1 = lstm_cell(P1[0], P1[1], P1[2], P1[3], qodd, c1r[un]);
                    if (last) {
                        float fw = fcw_s[u];
                        fc0 += hv0 * fw; fc1 += hv1 * fw;
                    } else {
                        __half h0h, h0l, h1h, h1l;
                        split16(hv0, h0h, h0l); split16(hv1, h1h, h1l);
                        if (t < 2) {
                            char* R0 = Awarp + row_e * ASTR;
                            char* R1 = Awarp + (row_e + 16) * ASTR;
                            *(__half*)(R0 + (50 + u) * 2)         = h0h;
                            *(__half*)(R0 + A_SEG + (50 + u) * 2) = h0l;
                            *(__half*)(R1 + (50 + u) * 2)         = h1h;
                            *(__half*)(R1 + A_SEG + (50 + u) * 2) = h1l;
                        }
                        if (l < L_LAYERS - 1) {
                            g_ys[((size_t)t * BTOT + grow0) * 50 + u] =
                                (u32)__half_as_ushort(h0h) | ((u32)__half_as_ushort(h0l) << 16);
                            g_ys[((size_t)t * BTOT + grow1) * 50 + u] =
                                (u32)__half_as_ushort(h1h) | ((u32)__half_as_ushort(h1l) << 16);
                        }
                    }
                }
            }
        }
    }

    fc0 += __shfl_xor_sync(0xffffffffu, fc0, 2);
    fc1 += __shfl_xor_sync(0xffffffffu, fc1, 2);
    if (q < 2) {
        float fb = fc_b[0];
        out[grow0] = fc0 + fb;
        out[grow1] = fc1 + fb;
    }
}

extern "C" void kernel_launch(void* const* d_in, const int* in_sizes, int n_in,
                              void* d_out, int out_size) {
    const float* x     = (const float*)d_in[0];
    const float* h0    = (const float*)d_in[1];
    const float* c0    = (const float*)d_in[2];
    const float* w_ih0 = (const float*)d_in[3];
    const float* w_ih  = (const float*)d_in[4];
    const float* w_hh  = (const float*)d_in[5];
    const float* b_ih  = (const float*)d_in[6];
    const float* b_hh  = (const float*)d_in[7];
    const float* fc_w  = (const float*)d_in[8];
    const float* fc_b  = (const float*)d_in[9];
    float* out = (float*)d_out;

    prep_kernel<<<(L_LAYERS * 200 * 120 + 255) / 256, 256>>>(w_ih0, w_ih, w_hh, b_ih, b_hh);

    static int once = 0;
    if (!once) {
        cudaFuncSetAttribute(lstm_hmma_kernel,
                             cudaFuncAttributeMaxDynamicSharedMemorySize, SMEM_BYTES);
        once = 1;
    }
    lstm_hmma_kernel<<<NCTA, NTH, SMEM_BYTES>>>(x, h0, c0, fc_w, fc_b, out);
}

// round 5
// speedup vs baseline: 2.3006x; 1.3510x over previous
#include <cuda_runtime.h>
#include <cuda_fp16.h>

#define BTOT     65536
#define ROWS_CTA 256
#define NCTA     (BTOT / ROWS_CTA)   // 256
#define NTH      512                 // 16 warps x 16 rows
#define L_LAYERS 6
#define KT       7                   // k16 tiles: [0..49 in][50..99 h][100 bias][101..111 pad]
#define ASTR     240                 // conflict-free stride (60r mod 32 distinct)

#define BSEG     48000               // 200 * 240 per seg (hi, lo)
#define A_OFF    96000
#define A_SEG    3840                // 16 rows * 240
#define AW_BYTES 7680                // hi+lo per warp
#define FCW_OFF  218880              // 96000 + 16*7680
#define SMEM_BYTES 219136

typedef unsigned u32;

__device__ __align__(16) char g_wB[L_LAYERS * 96000];   // fp16 hi/lo weights+bias, 240B rows
__device__ u32                g_ys[3ull * BTOT * 50];   // packed (hi,lo) hidden outputs

static __device__ __forceinline__ u32 smem_u32(const void* p) {
    u32 a;
    asm("{ .reg .u64 t; cvta.to.shared.u64 t, %1; cvt.u32.u64 %0, t; }" : "=r"(a) : "l"(p));
    return a;
}
static __device__ __forceinline__ void ldsm4(u32 addr, u32* r) {
    asm volatile("ldmatrix.sync.aligned.m8n8.x4.shared.b16 {%0,%1,%2,%3}, [%4];"
                 : "=r"(r[0]), "=r"(r[1]), "=r"(r[2]), "=r"(r[3]) : "r"(addr));
}
static __device__ __forceinline__ void ldsm2(u32 addr, u32* r) {
    asm volatile("ldmatrix.sync.aligned.m8n8.x2.shared.b16 {%0,%1}, [%2];"
                 : "=r"(r[0]), "=r"(r[1]) : "r"(addr));
}
static __device__ __forceinline__ void mma4(float* c, const u32* a, u32 b0, u32 b1) {
    asm("mma.sync.aligned.m16n8k16.row.col.f32.f16.f16.f32 "
        "{%0,%1,%2,%3},{%4,%5,%6,%7},{%8,%9},{%0,%1,%2,%3};"
        : "+f"(c[0]), "+f"(c[1]), "+f"(c[2]), "+f"(c[3])
        : "r"(a[0]), "r"(a[1]), "r"(a[2]), "r"(a[3]), "r"(b0), "r"(b1));
}
static __device__ __forceinline__ float rcpa(float x) {
    float r; asm("rcp.approx.f32 %0, %1;" : "=f"(r) : "f"(x)); return r;
}
static __device__ __forceinline__ void split16(float v, __half& hi, __half& lo) {
    hi = __float2half_rn(v);
    lo = __float2half_rn(v - __half2float(hi));
}
// fused LSTM cell: gates (bias already added via MMA), updates c, returns h
static __device__ __forceinline__ float lstm_cell(float a0, float a1, float a2, float a3,
                                                  int qodd, float& cst) {
    float sa = qodd ? a0 : a2; sa = __shfl_xor_sync(0xffffffffu, sa, 1);
    float sb = qodd ? a1 : a3; sb = __shfl_xor_sync(0xffffffffu, sb, 1);
    float gi, gf, gg, go;
    if (qodd) { gi = sa; gf = sb; gg = a2; go = a3; }
    else      { gi = a0; gf = a1; gg = sa; go = sb; }
    float e1 = __expf(-gi);
    float ef = __expf(-gf);
    float g2 = fminf(fmaxf(gg, -15.f), 15.f);
    float e2 = __expf(-2.f * g2);
    float cn = cst * rcpa(1.f + ef) + (1.f - e2) * rcpa((1.f + e1) * (1.f + e2));
    cst = cn;
    float cc = fminf(fmaxf(cn, -15.f), 15.f);
    float ec = __expf(-2.f * cc);
    float eo = __expf(-go);
    return (1.f - ec) * rcpa((1.f + eo) * (1.f + ec));
}

// ---------------- prep: weights+bias -> fp16 hi/lo, gate-interleaved, 240B rows ----------------
__global__ void prep_kernel(const float* __restrict__ w_ih0, const float* __restrict__ w_ih,
                            const float* __restrict__ w_hh,  const float* __restrict__ b_ih,
                            const float* __restrict__ b_hh) {
    int idx = blockIdx.x * 256 + threadIdx.x;
    if (idx >= L_LAYERS * 200 * 120) return;
    int k = idx % 120;
    int n = (idx / 120) % 200;
    int l = idx / (120 * 200);
    int u = n >> 2, g = n & 3, rt = g * 50 + u;
    float wv = 0.0f;
    if (k < 50)        wv = (l == 0) ? (k < 3 ? w_ih0[rt * 3 + k] : 0.0f)
                                     : w_ih[((size_t)(l - 1) * 200 + rt) * 50 + k];
    else if (k < 100)  wv = w_hh[((size_t)l * 200 + rt) * 50 + (k - 50)];
    else if (k == 100) wv = b_ih[l * 200 + rt] + b_hh[l * 200 + rt];
    __half hh, hl; split16(wv, hh, hl);
    __half* base = (__half*)(g_wB + (size_t)l * 96000);
    base[(size_t)n * 120 + k]         = hh;
    base[(size_t)(200 + n) * 120 + k] = hl;
}

// ---------------- main ----------------
__global__ void __launch_bounds__(NTH, 1) lstm_hmma_kernel(
    const float* __restrict__ x,    const float* __restrict__ h0,
    const float* __restrict__ c0,   const float* __restrict__ fc_w,
    const float* __restrict__ fc_b, float* __restrict__ out)
{
    extern __shared__ char smem[];
    const u32 sbase = smem_u32(smem);
    const int tid = threadIdx.x, lane = tid & 31, w = tid >> 5;
    const int q = lane & 3, r4 = lane >> 2, p = q >> 1, qodd = q & 1;
    const int row_e = r4 + 8 * qodd;
    const int wrb = blockIdx.x * ROWS_CTA + w * 16;
    const int grow = wrb + row_e;
    float* fcw_s = (float*)(smem + FCW_OFF);
    char* Awarp = smem + A_OFF + w * AW_BYTES;

    for (int i = tid; i < (16 * AW_BYTES) / 16; i += NTH)
        ((float4*)(smem + A_OFF))[i] = make_float4(0.f, 0.f, 0.f, 0.f);
    if (tid < 50) fcw_s[tid] = fc_w[tid];
    __syncthreads();
    if (lane < 16)
        *(__half*)(Awarp + lane * ASTR + 200) = __float2half(1.0f);   // bias col k=100

    const u32 aB  = sbase + A_OFF + w * AW_BYTES + (lane & 15) * ASTR + (lane >> 4) * 16;
    const u32 bB4 = sbase + (lane & 7) * ASTR + ((lane >> 3) & 1) * 16
                          + ((lane >> 4) & 1) * (8 * ASTR);

    float cr[25];
    float fcacc = 0.f;
    u32 afr[2][KT][4];

    #pragma unroll 1
    for (int l = 0; l < L_LAYERS; ++l) {
        __syncthreads();
        const float4* ws = (const float4*)(g_wB + (size_t)l * 96000);
        for (int i = tid; i < 6000; i += NTH) ((float4*)smem)[i] = __ldg(ws + i);
        __syncthreads();

        {   // h0 staging + c0 -> regs
            const int row = lane & 15;
            const float2* hp = (const float2*)(h0 + ((size_t)l * BTOT + wrb + row) * 50);
            char* Ar = Awarp + row * ASTR;
            for (int i = lane >> 4; i < 25; i += 2) {
                float2 v = hp[i];
                __half ah, al, bh_, bl_; split16(v.x, ah, al); split16(v.y, bh_, bl_);
                *(__half2*)(Ar + (50 + 2 * i) * 2)         = __halves2half2(ah, bh_);
                *(__half2*)(Ar + A_SEG + (50 + 2 * i) * 2) = __halves2half2(al, bl_);
            }
            const float* cp = c0 + ((size_t)l * BTOT + grow) * 50;
            #pragma unroll
            for (int un = 0; un < 25; ++un) cr[un] = cp[2 * un + p];
        }
        const bool l0 = (l == 0);

        #pragma unroll 1
        for (int t = 0; t < 3; ++t) {
            if (l0) {
                if (lane < 16) {
                    char* Ar = Awarp + lane * ASTR;
                    const float* xp = x + (size_t)(wrb + lane) * 9 + t;
                    __half a0, b0, a1, b1, a2, b2;
                    split16(xp[0], a0, b0); split16(xp[3], a1, b1); split16(xp[6], a2, b2);
                    *(__half2*)(Ar)            = __halves2half2(a0, a1);
                    *(__half*)(Ar + 4)         = a2;
                    *(__half2*)(Ar + A_SEG)    = __halves2half2(b0, b1);
                    *(__half*)(Ar + A_SEG + 4) = b2;
                }
            } else {
                const int row = lane & 15;
                char* Ar = Awarp + row * ASTR;
                const u32* yp = g_ys + ((size_t)t * BTOT + wrb + row) * 50;
                for (int i = lane >> 4; i < 25; i += 2) {
                    u32 y0 = yp[2 * i], y1 = yp[2 * i + 1];
                    *(__half2*)(Ar + 4 * i) = __halves2half2(
                        __ushort_as_half((unsigned short)y0), __ushort_as_half((unsigned short)y1));
                    *(__half2*)(Ar + A_SEG + 4 * i) = __halves2half2(
                        __ushort_as_half((unsigned short)(y0 >> 16)),
                        __ushort_as_half((unsigned short)(y1 >> 16)));
                }
            }
            __syncwarp();

            #pragma unroll
            for (int seg = 0; seg < 2; ++seg)
                #pragma unroll
                for (int kt = 0; kt < KT; ++kt)
                    ldsm4(aB + seg * A_SEG + kt * 32, afr[seg][kt]);

            const bool last = (l == L_LAYERS - 1) && (t == 2);

            #pragma unroll
            for (int j = 0; j < 13; ++j) {
                const u32 tb = bB4 + j * (16 * ASTR);
                if (j < 12) {
                    float A00[4] = {0.f,0.f,0.f,0.f}, A01[4] = {0.f,0.f,0.f,0.f};
                    #pragma unroll
                    for (int kt = 0; kt < KT; ++kt) {
                        if (l0 && (kt == 1 || kt == 2)) continue;   // all-zero tiles layer 0
                        u32 bh[4], bl[4];
                        ldsm4(tb + kt * 32, bh);
                        ldsm4(tb + BSEG + kt * 32, bl);
                        mma4(A00, afr[0][kt], bh[0], bh[1]);
                        mma4(A00, afr[1][kt], bh[0], bh[1]);
                        mma4(A00, afr[0][kt], bl[0], bl[1]);
                        mma4(A01, afr[0][kt], bh[2], bh[3]);
                        mma4(A01, afr[1][kt], bh[2], bh[3]);
                        mma4(A01, afr[0][kt], bl[2], bl[3]);
                    }
                    #pragma unroll
                    for (int nn = 0; nn < 2; ++nn) {
                        const int un = 2 * j + nn;
                        const int u = 2 * un + p;
                        const float* P = nn ? A01 : A00;
                        float hv = lstm_cell(P[0], P[1], P[2], P[3], qodd, cr[un]);
                        if (last) {
                            fcacc += hv * fcw_s[u];
                        } else {
                            __half hh, hl; split16(hv, hh, hl);
                            if (t < 2) {
                                char* R = Awarp + row_e * ASTR;
                                *(__half*)(R + (50 + u) * 2)         = hh;
                                *(__half*)(R + A_SEG + (50 + u) * 2) = hl;
                            }
                            if (l < L_LAYERS - 1)
                                g_ys[((size_t)t * BTOT + grow) * 50 + u] =
                                    (u32)__half_as_ushort(hh) | ((u32)__half_as_ushort(hl) << 16);
                        }
                    }
                } else {
                    float A00[4] = {0.f,0.f,0.f,0.f};
                    #pragma unroll
                    for (int kt = 0; kt < KT; ++kt) {
                        if (l0 && (kt == 1 || kt == 2)) continue;
                        u32 bh[2], bl[2];
                        ldsm2(tb + kt * 32, bh);
                        ldsm2(tb + BSEG + kt * 32, bl);
                        mma4(A00, afr[0][kt], bh[0], bh[1]);
                        mma4(A00, afr[1][kt], bh[0], bh[1]);
                        mma4(A00, afr[0][kt], bl[0], bl[1]);
                    }
                    const int un = 24;
                    const int u = 2 * un + p;
                    float hv = lstm_cell(A00[0], A00[1], A00[2], A00[3], qodd, cr[un]);
                    if (last) {
                        fcacc += hv * fcw_s[u];
                    } else {
                        __half hh, hl; split16(hv, hh, hl);
                        if (t < 2) {
                            char* R = Awarp + row_e * ASTR;
                            *(__half*)(R + (50 + u) * 2)         = hh;
                            *(__half*)(R + A_SEG + (50 + u) * 2) = hl;
                        }
                        if (l < L_LAYERS - 1)
                            g_ys[((size_t)t * BTOT + grow) * 50 + u] =
                                (u32)__half_as_ushort(hh) | ((u32)__half_as_ushort(hl) << 16);
                    }
                }
            }
        }
    }

    fcacc += __shfl_xor_sync(0xffffffffu, fcacc, 2);   // combine even/odd unit halves
    if (q < 2) out[grow] = fcacc + fc_b[0];
}

extern "C" void kernel_launch(void* const* d_in, const int* in_sizes, int n_in,
                              void* d_out, int out_size) {
    const float* x     = (const float*)d_in[0];
    const float* h0    = (const float*)d_in[1];
    const float* c0    = (const float*)d_in[2];
    const float* w_ih0 = (const float*)d_in[3];
    const float* w_ih  = (const float*)d_in[4];
    const float* w_hh  = (const float*)d_in[5];
    const float* b_ih  = (const float*)d_in[6];
    const float* b_hh  = (const float*)d_in[7];
    const float* fc_w  = (const float*)d_in[8];
    const float* fc_b  = (const float*)d_in[9];
    float* out = (float*)d_out;

    prep_kernel<<<(L_LAYERS * 200 * 120 + 255) / 256, 256>>>(w_ih0, w_ih, w_hh, b_ih, b_hh);

    static int once = 0;
    if (!once) {
        cudaFuncSetAttribute(lstm_hmma_kernel,
                             cudaFuncAttributeMaxDynamicSharedMemorySize, SMEM_BYTES);
        once = 1;
    }
    lstm_hmma_kernel<<<NCTA, NTH, SMEM_BYTES>>>(x, h0, c0, fc_w, fc_b, out);
}

// round 6
// speedup vs baseline: 2.9901x; 1.2997x over previous
#include <cuda_runtime.h>
#include <cuda_fp16.h>

#define BTOT     65536
#define ROWS_CTA 128
#define NCTA     (BTOT / ROWS_CTA)   // 512
#define NTH      256                 // 8 warps x 16 rows
#define L_LAYERS 6
#define KT       7                   // k16 tiles: [0..49 in][50..99 h][100 bias][101..111 pad]
#define ASTR     240                 // conflict-free stride (60r mod 32 distinct)

#define B_BYTES  48000               // 200 * 240, single fp16 seg
#define A_OFF    48000
#define A_SEG    3840                // 16 rows * 240
#define AW_BYTES 7680                // hi+lo per warp
#define FCW_OFF  109440              // 48000 + 8*7680
#define SMEM_BYTES 109696

typedef unsigned u32;

__device__ __align__(16) char g_wB[L_LAYERS * B_BYTES]; // fp16 weights+bias, 240B rows
__device__ u32                g_ys[3ull * BTOT * 50];   // packed (hi,lo) hidden outputs

static __device__ __forceinline__ u32 smem_u32(const void* p) {
    u32 a;
    asm("{ .reg .u64 t; cvta.to.shared.u64 t, %1; cvt.u32.u64 %0, t; }" : "=r"(a) : "l"(p));
    return a;
}
static __device__ __forceinline__ void ldsm4(u32 addr, u32* r) {
    asm volatile("ldmatrix.sync.aligned.m8n8.x4.shared.b16 {%0,%1,%2,%3}, [%4];"
                 : "=r"(r[0]), "=r"(r[1]), "=r"(r[2]), "=r"(r[3]) : "r"(addr));
}
static __device__ __forceinline__ void ldsm2(u32 addr, u32* r) {
    asm volatile("ldmatrix.sync.aligned.m8n8.x2.shared.b16 {%0,%1}, [%2];"
                 : "=r"(r[0]), "=r"(r[1]) : "r"(addr));
}
static __device__ __forceinline__ void mma4(float* c, const u32* a, u32 b0, u32 b1) {
    asm("mma.sync.aligned.m16n8k16.row.col.f32.f16.f16.f32 "
        "{%0,%1,%2,%3},{%4,%5,%6,%7},{%8,%9},{%0,%1,%2,%3};"
        : "+f"(c[0]), "+f"(c[1]), "+f"(c[2]), "+f"(c[3])
        : "r"(a[0]), "r"(a[1]), "r"(a[2]), "r"(a[3]), "r"(b0), "r"(b1));
}
static __device__ __forceinline__ float rcpa(float x) {
    float r; asm("rcp.approx.f32 %0, %1;" : "=f"(r) : "f"(x)); return r;
}
static __device__ __forceinline__ void split16(float v, __half& hi, __half& lo) {
    hi = __float2half_rn(v);
    lo = __float2half_rn(v - __half2float(hi));
}
// fused LSTM cell: gates (bias added via MMA), updates c, returns h
static __device__ __forceinline__ float lstm_cell(float a0, float a1, float a2, float a3,
                                                  int qodd, float& cst) {
    float sa = qodd ? a0 : a2; sa = __shfl_xor_sync(0xffffffffu, sa, 1);
    float sb = qodd ? a1 : a3; sb = __shfl_xor_sync(0xffffffffu, sb, 1);
    float gi, gf, gg, go;
    if (qodd) { gi = sa; gf = sb; gg = a2; go = a3; }
    else      { gi = a0; gf = a1; gg = sa; go = sb; }
    float e1 = __expf(-gi);
    float ef = __expf(-gf);
    float g2 = fminf(fmaxf(gg, -15.f), 15.f);
    float e2 = __expf(-2.f * g2);
    float cn = cst * rcpa(1.f + ef) + (1.f - e2) * rcpa((1.f + e1) * (1.f + e2));
    cst = cn;
    float cc = fminf(fmaxf(cn, -15.f), 15.f);
    float ec = __expf(-2.f * cc);
    float eo = __expf(-go);
    return (1.f - ec) * rcpa((1.f + eo) * (1.f + ec));
}

// ---------------- prep: weights+bias -> single fp16, gate-interleaved, 240B rows ----------------
__global__ void prep_kernel(const float* __restrict__ w_ih0, const float* __restrict__ w_ih,
                            const float* __restrict__ w_hh,  const float* __restrict__ b_ih,
                            const float* __restrict__ b_hh) {
    int idx = blockIdx.x * 256 + threadIdx.x;
    if (idx >= L_LAYERS * 200 * 120) return;
    int k = idx % 120;
    int n = (idx / 120) % 200;
    int l = idx / (120 * 200);
    int u = n >> 2, g = n & 3, rt = g * 50 + u;
    float wv = 0.0f;
    if (k < 50)        wv = (l == 0) ? (k < 3 ? w_ih0[rt * 3 + k] : 0.0f)
                                     : w_ih[((size_t)(l - 1) * 200 + rt) * 50 + k];
    else if (k < 100)  wv = w_hh[((size_t)l * 200 + rt) * 50 + (k - 50)];
    else if (k == 100) wv = b_ih[l * 200 + rt] + b_hh[l * 200 + rt];
    __half* base = (__half*)(g_wB + (size_t)l * B_BYTES);
    base[(size_t)n * 120 + k] = __float2half_rn(wv);
}

// ---------------- main ----------------
__global__ void __launch_bounds__(NTH, 2) lstm_hmma_kernel(
    const float* __restrict__ x,    const float* __restrict__ h0,
    const float* __restrict__ c0,   const float* __restrict__ fc_w,
    const float* __restrict__ fc_b, float* __restrict__ out)
{
    extern __shared__ char smem[];
    const u32 sbase = smem_u32(smem);
    const int tid = threadIdx.x, lane = tid & 31, w = tid >> 5;
    const int q = lane & 3, r4 = lane >> 2, p = q >> 1, qodd = q & 1;
    const int row_e = r4 + 8 * qodd;
    const int wrb = blockIdx.x * ROWS_CTA + w * 16;
    const int grow = wrb + row_e;
    float* fcw_s = (float*)(smem + FCW_OFF);
    char* Awarp = smem + A_OFF + w * AW_BYTES;

    for (int i = tid; i < (8 * AW_BYTES) / 16; i += NTH)
        ((float4*)(smem + A_OFF))[i] = make_float4(0.f, 0.f, 0.f, 0.f);
    if (tid < 50) fcw_s[tid] = fc_w[tid];
    __syncthreads();
    if (lane < 16)
        *(__half*)(Awarp + lane * ASTR + 200) = __float2half(1.0f);   // bias col k=100

    const u32 aB  = sbase + A_OFF + w * AW_BYTES + (lane & 15) * ASTR + (lane >> 4) * 16;
    const u32 bB4 = sbase + (lane & 7) * ASTR + ((lane >> 3) & 1) * 16
                          + ((lane >> 4) & 1) * (8 * ASTR);

    float cr[25];
    float fcacc = 0.f;
    u32 afr[2][KT][4];

    #pragma unroll 1
    for (int l = 0; l < L_LAYERS; ++l) {
        __syncthreads();
        const float4* ws = (const float4*)(g_wB + (size_t)l * B_BYTES);
        for (int i = tid; i < B_BYTES / 16; i += NTH) ((float4*)smem)[i] = __ldg(ws + i);
        __syncthreads();

        {   // h0 staging + c0 -> regs
            const int row = lane & 15;
            const float2* hp = (const float2*)(h0 + ((size_t)l * BTOT + wrb + row) * 50);
            char* Ar = Awarp + row * ASTR;
            for (int i = lane >> 4; i < 25; i += 2) {
                float2 v = hp[i];
                __half ah, al, bh_, bl_; split16(v.x, ah, al); split16(v.y, bh_, bl_);
                *(__half2*)(Ar + (50 + 2 * i) * 2)         = __halves2half2(ah, bh_);
                *(__half2*)(Ar + A_SEG + (50 + 2 * i) * 2) = __halves2half2(al, bl_);
            }
            const float* cp = c0 + ((size_t)l * BTOT + grow) * 50;
            #pragma unroll
            for (int un = 0; un < 25; ++un) cr[un] = cp[2 * un + p];
        }
        const bool l0 = (l == 0);

        #pragma unroll 1
        for (int t = 0; t < 3; ++t) {
            if (l0) {
                if (lane < 16) {
                    char* Ar = Awarp + lane * ASTR;
                    const float* xp = x + (size_t)(wrb + lane) * 9 + t;
                    __half a0, b0, a1, b1, a2, b2;
                    split16(xp[0], a0, b0); split16(xp[3], a1, b1); split16(xp[6], a2, b2);
                    *(__half2*)(Ar)            = __halves2half2(a0, a1);
                    *(__half*)(Ar + 4)         = a2;
                    *(__half2*)(Ar + A_SEG)    = __halves2half2(b0, b1);
                    *(__half*)(Ar + A_SEG + 4) = b2;
                }
            } else {
                const int row = lane & 15;
                char* Ar = Awarp + row * ASTR;
                const u32* yp = g_ys + ((size_t)t * BTOT + wrb + row) * 50;
                for (int i = lane >> 4; i < 25; i += 2) {
                    u32 y0 = yp[2 * i], y1 = yp[2 * i + 1];
                    *(__half2*)(Ar + 4 * i) = __halves2half2(
                        __ushort_as_half((unsigned short)y0), __ushort_as_half((unsigned short)y1));
                    *(__half2*)(Ar + A_SEG + 4 * i) = __halves2half2(
                        __ushort_as_half((unsigned short)(y0 >> 16)),
                        __ushort_as_half((unsigned short)(y1 >> 16)));
                }
            }
            __syncwarp();

            #pragma unroll
            for (int seg = 0; seg < 2; ++seg)
                #pragma unroll
                for (int kt = 0; kt < KT; ++kt)
                    ldsm4(aB + seg * A_SEG + kt * 32, afr[seg][kt]);

            const bool last = (l == L_LAYERS - 1) && (t == 2);

            #pragma unroll
            for (int j = 0; j < 13; ++j) {
                const u32 tb = bB4 + j * (16 * ASTR);
                if (j < 12) {
                    float A00[4] = {0.f,0.f,0.f,0.f}, A01[4] = {0.f,0.f,0.f,0.f};
                    #pragma unroll
                    for (int kt = 0; kt < KT; ++kt) {
                        if (l0 && (kt == 1 || kt == 2)) continue;   // all-zero tiles layer 0
                        u32 bh[4];
                        ldsm4(tb + kt * 32, bh);
                        mma4(A00, afr[0][kt], bh[0], bh[1]);
                        mma4(A00, afr[1][kt], bh[0], bh[1]);
                        mma4(A01, afr[0][kt], bh[2], bh[3]);
                        mma4(A01, afr[1][kt], bh[2], bh[3]);
                    }
                    #pragma unroll
                    for (int nn = 0; nn < 2; ++nn) {
                        const int un = 2 * j + nn;
                        const int u = 2 * un + p;
                        const float* P = nn ? A01 : A00;
                        float hv = lstm_cell(P[0], P[1], P[2], P[3], qodd, cr[un]);
                        if (last) {
                            fcacc += hv * fcw_s[u];
                        } else {
                            __half hh, hl; split16(hv, hh, hl);
                            if (t < 2) {
                                char* R = Awarp + row_e * ASTR;
                                *(__half*)(R + (50 + u) * 2)         = hh;
                                *(__half*)(R + A_SEG + (50 + u) * 2) = hl;
                            }
                            if (l < L_LAYERS - 1)
                                g_ys[((size_t)t * BTOT + grow) * 50 + u] =
                                    (u32)__half_as_ushort(hh) | ((u32)__half_as_ushort(hl) << 16);
                        }
                    }
                } else {
                    float A00[4] = {0.f,0.f,0.f,0.f};
                    #pragma unroll
                    for (int kt = 0; kt < KT; ++kt) {
                        if (l0 && (kt == 1 || kt == 2)) continue;
                        u32 bh[2];
                        ldsm2(tb + kt * 32, bh);
                        mma4(A00, afr[0][kt], bh[0], bh[1]);
                        mma4(A00, afr[1][kt], bh[0], bh[1]);
                    }
                    const int un = 24;
                    const int u = 2 * un + p;
                    float hv = lstm_cell(A00[0], A00[1], A00[2], A00[3], qodd, cr[un]);
                    if (last) {
                        fcacc += hv * fcw_s[u];
                    } else {
                        __half hh, hl; split16(hv, hh, hl);
                        if (t < 2) {
                            char* R = Awarp + row_e * ASTR;
                            *(__half*)(R + (50 + u) * 2)         = hh;
                            *(__half*)(R + A_SEG + (50 + u) * 2) = hl;
                        }
                        if (l < L_LAYERS - 1)
                            g_ys[((size_t)t * BTOT + grow) * 50 + u] =
                                (u32)__half_as_ushort(hh) | ((u32)__half_as_ushort(hl) << 16);
                    }
                }
            }
        }
    }

    fcacc += __shfl_xor_sync(0xffffffffu, fcacc, 2);   // combine even/odd unit halves
    if (q < 2) out[grow] = fcacc + fc_b[0];
}

extern "C" void kernel_launch(void* const* d_in, const int* in_sizes, int n_in,
                              void* d_out, int out_size) {
    const float* x     = (const float*)d_in[0];
    const float* h0    = (const float*)d_in[1];
    const float* c0    = (const float*)d_in[2];
    const float* w_ih0 = (const float*)d_in[3];
    const float* w_ih  = (const float*)d_in[4];
    const float* w_hh  = (const float*)d_in[5];
    const float* b_ih  = (const float*)d_in[6];
    const float* b_hh  = (const float*)d_in[7];
    const float* fc_w  = (const float*)d_in[8];
    const float* fc_b  = (const float*)d_in[9];
    float* out = (float*)d_out;

    prep_kernel<<<(L_LAYERS * 200 * 120 + 255) / 256, 256>>>(w_ih0, w_ih, w_hh, b_ih, b_hh);

    static int once = 0;
    if (!once) {
        cudaFuncSetAttribute(lstm_hmma_kernel,
                             cudaFuncAttributeMaxDynamicSharedMemorySize, SMEM_BYTES);
        once = 1;
    }
    lstm_hmma_kernel<<<NCTA, NTH, SMEM_BYTES>>>(x, h0, c0, fc_w, fc_b, out);
}

// round 7
// speedup vs baseline: 4.0029x; 1.3387x over previous
#include <cuda_runtime.h>
#include <cuda_fp16.h>

#define BTOT     65536
#define ROWS_CTA 128
#define NCTA     (BTOT / ROWS_CTA)   // 512
#define NTH      256                 // 8 warps x 16 rows
#define L_LAYERS 6
#define KT       7                   // k16 tiles: [0..49 in][50..99 h][100 bias][101..111 pad]
#define ASTR     240                 // conflict-free stride (60r mod 32 distinct)

#define B_BYTES  48000               // 200 * 240 fp16
#define A_OFF    48000
#define A_SEG    3840                // 16 rows * 240 (single hi seg)
#define FCW_OFF  78720               // 48000 + 8*3840
#define SMEM_BYTES 78976

typedef unsigned u32;
typedef unsigned short u16;

__device__ __align__(16) char g_wB[L_LAYERS * B_BYTES]; // fp16 weights+bias, 240B rows
__device__ u16                g_ys[3ull * BTOT * 50];   // fp16 hidden outputs

static __device__ __forceinline__ u32 smem_u32(const void* p) {
    u32 a;
    asm("{ .reg .u64 t; cvta.to.shared.u64 t, %1; cvt.u32.u64 %0, t; }" : "=r"(a) : "l"(p));
    return a;
}
static __device__ __forceinline__ void ldsm4(u32 addr, u32* r) {
    asm volatile("ldmatrix.sync.aligned.m8n8.x4.shared.b16 {%0,%1,%2,%3}, [%4];"
                 : "=r"(r[0]), "=r"(r[1]), "=r"(r[2]), "=r"(r[3]) : "r"(addr));
}
static __device__ __forceinline__ void ldsm2(u32 addr, u32* r) {
    asm volatile("ldmatrix.sync.aligned.m8n8.x2.shared.b16 {%0,%1}, [%2];"
                 : "=r"(r[0]), "=r"(r[1]) : "r"(addr));
}
static __device__ __forceinline__ void mma4(float* c, const u32* a, u32 b0, u32 b1) {
    asm("mma.sync.aligned.m16n8k16.row.col.f32.f16.f16.f32 "
        "{%0,%1,%2,%3},{%4,%5,%6,%7},{%8,%9},{%0,%1,%2,%3};"
        : "+f"(c[0]), "+f"(c[1]), "+f"(c[2]), "+f"(c[3])
        : "r"(a[0]), "r"(a[1]), "r"(a[2]), "r"(a[3]), "r"(b0), "r"(b1));
}
static __device__ __forceinline__ float rcpa(float x) {
    float r; asm("rcp.approx.f32 %0, %1;" : "=f"(r) : "f"(x)); return r;
}
// fused LSTM cell: gates (bias added via MMA), updates c, returns h
static __device__ __forceinline__ float lstm_cell(float a0, float a1, float a2, float a3,
                                                  int qodd, float& cst) {
    float sa = qodd ? a0 : a2; sa = __shfl_xor_sync(0xffffffffu, sa, 1);
    float sb = qodd ? a1 : a3; sb = __shfl_xor_sync(0xffffffffu, sb, 1);
    float gi, gf, gg, go;
    if (qodd) { gi = sa; gf = sb; gg = a2; go = a3; }
    else      { gi = a0; gf = a1; gg = sa; go = sb; }
    float e1 = __expf(-gi);
    float ef = __expf(-gf);
    float g2 = fminf(fmaxf(gg, -15.f), 15.f);
    float e2 = __expf(-2.f * g2);
    float cn = cst * rcpa(1.f + ef) + (1.f - e2) * rcpa((1.f + e1) * (1.f + e2));
    cst = cn;
    float cc = fminf(fmaxf(cn, -15.f), 15.f);
    float ec = __expf(-2.f * cc);
    float eo = __expf(-go);
    return (1.f - ec) * rcpa((1.f + eo) * (1.f + ec));
}

// ---------------- prep: weights+bias -> fp16, gate-interleaved, 240B rows ----------------
__global__ void prep_kernel(const float* __restrict__ w_ih0, const float* __restrict__ w_ih,
                            const float* __restrict__ w_hh,  const float* __restrict__ b_ih,
                            const float* __restrict__ b_hh) {
    int idx = blockIdx.x * 256 + threadIdx.x;
    if (idx >= L_LAYERS * 200 * 120) return;
    int k = idx % 120;
    int n = (idx / 120) % 200;
    int l = idx / (120 * 200);
    int u = n >> 2, g = n & 3, rt = g * 50 + u;
    float wv = 0.0f;
    if (k < 50)        wv = (l == 0) ? (k < 3 ? w_ih0[rt * 3 + k] : 0.0f)
                                     : w_ih[((size_t)(l - 1) * 200 + rt) * 50 + k];
    else if (k < 100)  wv = w_hh[((size_t)l * 200 + rt) * 50 + (k - 50)];
    else if (k == 100) wv = b_ih[l * 200 + rt] + b_hh[l * 200 + rt];
    __half* base = (__half*)(g_wB + (size_t)l * B_BYTES);
    base[(size_t)n * 120 + k] = __float2half_rn(wv);
}

// ---------------- main ----------------
__global__ void __launch_bounds__(NTH, 2) lstm_hmma_kernel(
    const float* __restrict__ x,    const float* __restrict__ h0,
    const float* __restrict__ c0,   const float* __restrict__ fc_w,
    const float* __restrict__ fc_b, float* __restrict__ out)
{
    extern __shared__ char smem[];
    const u32 sbase = smem_u32(smem);
    const int tid = threadIdx.x, lane = tid & 31, w = tid >> 5;
    const int q = lane & 3, r4 = lane >> 2, p = q >> 1, qodd = q & 1;
    const int row_e = r4 + 8 * qodd;
    const int wrb = blockIdx.x * ROWS_CTA + w * 16;
    const int grow = wrb + row_e;
    float* fcw_s = (float*)(smem + FCW_OFF);
    char* Awarp = smem + A_OFF + w * A_SEG;

    for (int i = tid; i < (8 * A_SEG) / 16; i += NTH)
        ((float4*)(smem + A_OFF))[i] = make_float4(0.f, 0.f, 0.f, 0.f);
    if (tid < 50) fcw_s[tid] = fc_w[tid];
    __syncthreads();
    if (lane < 16)
        *(__half*)(Awarp + lane * ASTR + 200) = __float2half(1.0f);   // bias col k=100

    const u32 aB  = sbase + A_OFF + w * A_SEG + (lane & 15) * ASTR + (lane >> 4) * 16;
    const u32 bB4 = sbase + (lane & 7) * ASTR + ((lane >> 3) & 1) * 16
                          + ((lane >> 4) & 1) * (8 * ASTR);

    float cr[25];
    float fcacc = 0.f;
    u32 afr[KT][4];

    #pragma unroll 1
    for (int l = 0; l < L_LAYERS; ++l) {
        __syncthreads();
        const float4* ws = (const float4*)(g_wB + (size_t)l * B_BYTES);
        for (int i = tid; i < B_BYTES / 16; i += NTH) ((float4*)smem)[i] = __ldg(ws + i);
        __syncthreads();

        {   // h0 staging (fp16 hi only) + c0 -> regs
            const int row = lane & 15;
            const float2* hp = (const float2*)(h0 + ((size_t)l * BTOT + wrb + row) * 50);
            char* Ar = Awarp + row * ASTR;
            for (int i = lane >> 4; i < 25; i += 2) {
                float2 v = hp[i];
                *(__half2*)(Ar + (50 + 2 * i) * 2) =
                    __halves2half2(__float2half_rn(v.x), __float2half_rn(v.y));
            }
            const float* cp = c0 + ((size_t)l * BTOT + grow) * 50;
            #pragma unroll
            for (int un = 0; un < 25; ++un) cr[un] = cp[2 * un + p];
        }
        const bool l0 = (l == 0);

        #pragma unroll 1
        for (int t = 0; t < 3; ++t) {
            if (l0) {
                if (lane < 16) {
                    char* Ar = Awarp + lane * ASTR;
                    const float* xp = x + (size_t)(wrb + lane) * 9 + t;
                    *(__half2*)(Ar) = __halves2half2(__float2half_rn(xp[0]),
                                                     __float2half_rn(xp[3]));
                    *(__half*)(Ar + 4) = __float2half_rn(xp[6]);
                }
            } else {
                const int row = lane & 15;
                char* Ar = Awarp + row * ASTR;
                const u32* yp = (const u32*)(g_ys + ((size_t)t * BTOT + wrb + row) * 50);
                for (int i = lane >> 4; i < 25; i += 2)
                    *(u32*)(Ar + 4 * i) = yp[i];      // 2 fp16 at a time
            }
            __syncwarp();

            #pragma unroll
            for (int kt = 0; kt < KT; ++kt)
                ldsm4(aB + kt * 32, afr[kt]);

            const bool last = (l == L_LAYERS - 1) && (t == 2);

            #pragma unroll
            for (int j = 0; j < 13; ++j) {
                const u32 tb = bB4 + j * (16 * ASTR);
                if (j < 12) {
                    float A00[4] = {0.f,0.f,0.f,0.f}, A01[4] = {0.f,0.f,0.f,0.f};
                    #pragma unroll
                    for (int kt = 0; kt < KT; ++kt) {
                        if (l0 && (kt == 1 || kt == 2)) continue;   // all-zero tiles layer 0
                        u32 bh[4];
                        ldsm4(tb + kt * 32, bh);
                        mma4(A00, afr[kt], bh[0], bh[1]);
                        mma4(A01, afr[kt], bh[2], bh[3]);
                    }
                    #pragma unroll
                    for (int nn = 0; nn < 2; ++nn) {
                        const int un = 2 * j + nn;
                        const int u = 2 * un + p;
                        const float* P = nn ? A01 : A00;
                        float hv = lstm_cell(P[0], P[1], P[2], P[3], qodd, cr[un]);
                        if (last) {
                            fcacc += hv * fcw_s[u];
                        } else {
                            __half hh = __float2half_rn(hv);
                            if (t < 2)
                                *(__half*)(Awarp + row_e * ASTR + (50 + u) * 2) = hh;
                            if (l < L_LAYERS - 1)
                                g_ys[((size_t)t * BTOT + grow) * 50 + u] = __half_as_ushort(hh);
                        }
                    }
                } else {
                    float A00[4] = {0.f,0.f,0.f,0.f};
                    #pragma unroll
                    for (int kt = 0; kt < KT; ++kt) {
                        if (l0 && (kt == 1 || kt == 2)) continue;
                        u32 bh[2];
                        ldsm2(tb + kt * 32, bh);
                        mma4(A00, afr[kt], bh[0], bh[1]);
                    }
                    const int un = 24;
                    const int u = 2 * un + p;
                    float hv = lstm_cell(A00[0], A00[1], A00[2], A00[3], qodd, cr[un]);
                    if (last) {
                        fcacc += hv * fcw_s[u];
                    } else {
                        __half hh = __float2half_rn(hv);
                        if (t < 2)
                            *(__half*)(Awarp + row_e * ASTR + (50 + u) * 2) = hh;
                        if (l < L_LAYERS - 1)
                            g_ys[((size_t)t * BTOT + grow) * 50 + u] = __half_as_ushort(hh);
                    }
                }
            }
        }
    }

    fcacc += __shfl_xor_sync(0xffffffffu, fcacc, 2);   // combine even/odd unit halves
    if (q < 2) out[grow] = fcacc + fc_b[0];
}

extern "C" void kernel_launch(void* const* d_in, const int* in_sizes, int n_in,
                              void* d_out, int out_size) {
    const float* x     = (const float*)d_in[0];
    const float* h0    = (const float*)d_in[1];
    const float* c0    = (const float*)d_in[2];
    const float* w_ih0 = (const float*)d_in[3];
    const float* w_ih  = (const float*)d_in[4];
    const float* w_hh  = (const float*)d_in[5];
    const float* b_ih  = (const float*)d_in[6];
    const float* b_hh  = (const float*)d_in[7];
    const float* fc_w  = (const float*)d_in[8];
    const float* fc_b  = (const float*)d_in[9];
    float* out = (float*)d_out;

    prep_kernel<<<(L_LAYERS * 200 * 120 + 255) / 256, 256>>>(w_ih0, w_ih, w_hh, b_ih, b_hh);

    static int once = 0;
    if (!once) {
        cudaFuncSetAttribute(lstm_hmma_kernel,
                             cudaFuncAttributeMaxDynamicSharedMemorySize, SMEM_BYTES);
        once = 1;
    }
    lstm_hmma_kernel<<<NCTA, NTH, SMEM_BYTES>>>(x, h0, c0, fc_w, fc_b, out);
}

// round 8
// speedup vs baseline: 4.0082x; 1.0013x over previous
#include <cuda_runtime.h>
#include <cuda_fp16.h>

#define BTOT     65536
#define ROWS_CTA 128
#define NCTA     (BTOT / ROWS_CTA)   // 512
#define NTH      256                 // 8 warps = 4 pairs x 32 rows
#define NPAIR    4
#define L_LAYERS 6
#define KT       7                   // k16 tiles: [0..49 in][50..99 h][100 bias][101..111 pad]
#define ASTR     240                 // conflict-free stride (60r mod 32 distinct)
#define NB       208                 // padded gate columns (13 blocks of 16)

#define B_BYTES  (NB * ASTR)              // 49920
#define A_OFF    B_BYTES
#define APAIR    (32 * ASTR)              // 7680
#define FCO_OFF  (A_OFF + NPAIR * APAIR)  // 80640
#define FCW_OFF  (FCO_OFF + 128 * 4)      // 81152
#define SMEM_BYTES 81408

typedef unsigned u32;
typedef unsigned short u16;

__device__ __align__(16) char g_wB[L_LAYERS * B_BYTES]; // fp16 weights+bias, 240B rows
__device__ u16                g_ys[3ull * BTOT * 50];   // fp16 hidden outputs

static __device__ __forceinline__ u32 smem_u32(const void* p) {
    u32 a;
    asm("{ .reg .u64 t; cvta.to.shared.u64 t, %1; cvt.u32.u64 %0, t; }" : "=r"(a) : "l"(p));
    return a;
}
static __device__ __forceinline__ void ldsm4(u32 addr, u32* r) {
    asm volatile("ldmatrix.sync.aligned.m8n8.x4.shared.b16 {%0,%1,%2,%3}, [%4];"
                 : "=r"(r[0]), "=r"(r[1]), "=r"(r[2]), "=r"(r[3]) : "r"(addr));
}
static __device__ __forceinline__ void mma4(float* c, const u32* a, u32 b0, u32 b1) {
    asm("mma.sync.aligned.m16n8k16.row.col.f32.f16.f16.f32 "
        "{%0,%1,%2,%3},{%4,%5,%6,%7},{%8,%9},{%0,%1,%2,%3};"
        : "+f"(c[0]), "+f"(c[1]), "+f"(c[2]), "+f"(c[3])
        : "r"(a[0]), "r"(a[1]), "r"(a[2]), "r"(a[3]), "r"(b0), "r"(b1));
}
static __device__ __forceinline__ float rcpa(float x) {
    float r; asm("rcp.approx.f32 %0, %1;" : "=f"(r) : "f"(x)); return r;
}
#define BARP(id) asm volatile("bar.sync %0, 64;" :: "r"(id) : "memory")

// shfl-free LSTM cell: all 4 gates thread-local (bias folded into MMA)
static __device__ __forceinline__ float lstm_cell(float gi, float gf, float gg, float go,
                                                  float& cst) {
    float e1 = __expf(-gi);
    float ef = __expf(-gf);
    float g2 = fminf(fmaxf(gg, -15.f), 15.f);
    float e2 = __expf(-2.f * g2);
    float cn = cst * rcpa(1.f + ef) + (1.f - e2) * rcpa((1.f + e1) * (1.f + e2));
    cst = cn;
    float cc = fminf(fmaxf(cn, -15.f), 15.f);
    float ec = __expf(-2.f * cc);
    float eo = __expf(-go);
    return (1.f - ec) * rcpa((1.f + eo) * (1.f + ec));
}

// ---------------- prep: weights+bias -> fp16, shfl-free gate layout, 240B rows ----------------
// col n -> unit = 4*(n>>4) + ((n&7)>>1), gate = (n&1) + 2*((n>>3)&1); units >=50 are zero pad.
__global__ void prep_kernel(const float* __restrict__ w_ih0, const float* __restrict__ w_ih,
                            const float* __restrict__ w_hh,  const float* __restrict__ b_ih,
                            const float* __restrict__ b_hh) {
    int idx = blockIdx.x * 256 + threadIdx.x;
    if (idx >= L_LAYERS * NB * 120) return;
    int k = idx % 120;
    int n = (idx / 120) % NB;
    int l = idx / (120 * NB);
    int u = 4 * (n >> 4) + ((n & 7) >> 1);
    int g = (n & 1) + 2 * ((n >> 3) & 1);
    float wv = 0.0f;
    if (u < 50) {
        int rt = g * 50 + u;
        if (k < 50)        wv = (l == 0) ? (k < 3 ? w_ih0[rt * 3 + k] : 0.0f)
                                         : w_ih[((size_t)(l - 1) * 200 + rt) * 50 + k];
        else if (k < 100)  wv = w_hh[((size_t)l * 200 + rt) * 50 + (k - 50)];
        else if (k == 100) wv = b_ih[l * 200 + rt] + b_hh[l * 200 + rt];
    }
    __half* base = (__half*)(g_wB + (size_t)l * B_BYTES);
    base[(size_t)n * 120 + k] = __float2half_rn(wv);
}

// ---------------- main ----------------
__global__ void __launch_bounds__(NTH, 2) lstm_hmma_kernel(
    const float* __restrict__ x,    const float* __restrict__ h0,
    const float* __restrict__ c0,   const float* __restrict__ fc_w,
    const float* __restrict__ fc_b, float* __restrict__ out)
{
    extern __shared__ char smem[];
    const u32 sbase = smem_u32(smem);
    const int tid = threadIdx.x, lane = tid & 31, w = tid >> 5;
    const int sub = w & 1, pid = w >> 1;
    const int q = lane & 3, r4 = lane >> 2;
    const int boff = blockIdx.x * ROWS_CTA;
    const int prb = boff + pid * 32;              // pair's global row base
    const int jbase = sub * 7;                    // sub0: j0..6, sub1: j7..12
    const int barid = 1 + pid;
    float* fcw_s = (float*)(smem + FCW_OFF);
    float* fcout = (float*)(smem + FCO_OFF);
    char* Apair = smem + A_OFF + pid * APAIR;

    for (int i = tid; i < (NPAIR * APAIR) / 16; i += NTH)
        ((float4*)(smem + A_OFF))[i] = make_float4(0.f, 0.f, 0.f, 0.f);
    if (tid < 50) fcw_s[tid] = fc_w[tid];
    if (tid < 128) fcout[tid] = 0.f;
    __syncthreads();
    if (sub == 0)
        *(__half*)(Apair + lane * ASTR + 200) = __float2half(1.0f);   // bias col k=100

    const u32 aB  = sbase + A_OFF + pid * APAIR + (lane & 15) * ASTR + (lane >> 4) * 16;
    const u32 bB4 = sbase + (lane & 7) * ASTR + ((lane >> 3) & 1) * 16
                          + ((lane >> 4) & 1) * (8 * ASTR);

    float cr[28];          // [jj*4 + mt*2 + h8]
    float fca[4] = {0.f, 0.f, 0.f, 0.f};
    u32 afr[2][KT][4];     // [m16 tile][k tile]

    #pragma unroll 1
    for (int l = 0; l < L_LAYERS; ++l) {
        __syncthreads();
        const float4* ws = (const float4*)(g_wB + (size_t)l * B_BYTES);
        for (int i = tid; i < B_BYTES / 16; i += NTH) ((float4*)smem)[i] = __ldg(ws + i);
        __syncthreads();

        // layer init: h0 -> A cols 50..99, c0 -> cr
        for (int idx = lane + 32 * sub; idx < 800; idx += 64) {
            int row = idx / 25, i = idx % 25;
            float2 v = *(const float2*)(h0 + ((size_t)l * BTOT + prb + row) * 50 + 2 * i);
            *(__half2*)(Apair + row * ASTR + 100 + 4 * i) =
                __halves2half2(__float2half_rn(v.x), __float2half_rn(v.y));
        }
        {
            const float* cp = c0 + ((size_t)l * BTOT + prb) * 50;
            #pragma unroll
            for (int jj = 0; jj < 7; ++jj) {
                int j = jbase + jj;
                if (j > 12) break;
                int u = 4 * j + q;
                if (u < 50) {
                    #pragma unroll
                    for (int mt = 0; mt < 2; ++mt)
                        #pragma unroll
                        for (int h8 = 0; h8 < 2; ++h8) {
                            int row = r4 + 8 * h8 + 16 * mt;
                            cr[jj * 4 + mt * 2 + h8] = cp[(size_t)row * 50 + u];
                        }
                }
            }
        }
        const bool l0 = (l == 0);

        #pragma unroll 1
        for (int t = 0; t < 3; ++t) {
            // phase 1: stage A input cols 0..49
            if (l0) {
                if (sub == 0) {
                    char* Ar = Apair + lane * ASTR;
                    const float* xp = x + (size_t)(prb + lane) * 9 + t;
                    *(__half2*)(Ar) = __halves2half2(__float2half_rn(xp[0]),
                                                     __float2half_rn(xp[3]));
                    *(__half*)(Ar + 4) = __float2half_rn(xp[6]);
                }
            } else {
                for (int idx = lane + 32 * sub; idx < 800; idx += 64) {
                    int row = idx / 25, i = idx % 25;
                    *(u32*)(Apair + row * ASTR + 4 * i) =
                        ((const u32*)(g_ys + ((size_t)t * BTOT + prb + row) * 50))[i];
                }
            }
            BARP(barid);                               // staging + prev h-writes visible

            #pragma unroll
            for (int mt = 0; mt < 2; ++mt)
                #pragma unroll
                for (int kt = 0; kt < KT; ++kt)
                    ldsm4(aB + mt * (16 * ASTR) + kt * 32, afr[mt][kt]);
            BARP(barid);                               // A consumed; h-writes now safe

            const bool last = (l == L_LAYERS - 1) && (t == 2);

            #pragma unroll
            for (int jj = 0; jj < 7; ++jj) {
                int j = jbase + jj;
                if (j > 12) break;
                float acc[2][8] = {{0.f,0.f,0.f,0.f,0.f,0.f,0.f,0.f},
                                   {0.f,0.f,0.f,0.f,0.f,0.f,0.f,0.f}};
                const u32 tb = bB4 + j * (16 * ASTR);
                #pragma unroll
                for (int kt = 0; kt < KT; ++kt) {
                    if (l0 && (kt == 1 || kt == 2)) continue;   // all-zero tiles layer 0
                    u32 bh[4];
                    ldsm4(tb + kt * 32, bh);
                    mma4(acc[0] + 0, afr[0][kt], bh[0], bh[1]);
                    mma4(acc[0] + 4, afr[0][kt], bh[2], bh[3]);
                    mma4(acc[1] + 0, afr[1][kt], bh[0], bh[1]);
                    mma4(acc[1] + 4, afr[1][kt], bh[2], bh[3]);
                }
                const int u = 4 * j + q;
                if (u < 50) {
                    const float fw = fcw_s[u];
                    #pragma unroll
                    for (int mt = 0; mt < 2; ++mt)
                        #pragma unroll
                        for (int h8 = 0; h8 < 2; ++h8) {
                            float gi = acc[mt][h8 * 2 + 0];
                            float gf = acc[mt][h8 * 2 + 1];
                            float gg = acc[mt][4 + h8 * 2 + 0];
                            float go = acc[mt][4 + h8 * 2 + 1];
                            float hv = lstm_cell(gi, gf, gg, go, cr[jj * 4 + mt * 2 + h8]);
                            int row = r4 + 8 * h8 + 16 * mt;
                            if (last) {
                                fca[mt * 2 + h8] += hv * fw;
                            } else {
                                __half hh = __float2half_rn(hv);
                                if (t < 2)
                                    *(__half*)(Apair + row * ASTR + (50 + u) * 2) = hh;
                                if (l < L_LAYERS - 1)
                                    g_ys[((size_t)t * BTOT + prb + row) * 50 + u] =
                                        __half_as_ushort(hh);
                            }
                        }
                }
            }
            if (last) {   // reduce FC partials across q, accumulate per row
                #pragma unroll
                for (int i = 0; i < 4; ++i) {
                    fca[i] += __shfl_xor_sync(0xffffffffu, fca[i], 1);
                    fca[i] += __shfl_xor_sync(0xffffffffu, fca[i], 2);
                }
                if (q == 0) {
                    #pragma unroll
                    for (int mt = 0; mt < 2; ++mt)
                        #pragma unroll
                        for (int h8 = 0; h8 < 2; ++h8)
                            atomicAdd(&fcout[pid * 32 + r4 + 8 * h8 + 16 * mt],
                                      fca[mt * 2 + h8]);
                }
            }
        }
    }

    __syncthreads();
    if (tid < 128) out[boff + tid] = fcout[tid] + fc_b[0];
}

extern "C" void kernel_launch(void* const* d_in, const int* in_sizes, int n_in,
                              void* d_out, int out_size) {
    const float* x     = (const float*)d_in[0];
    const float* h0    = (const float*)d_in[1];
    const float* c0    = (const float*)d_in[2];
    const float* w_ih0 = (const float*)d_in[3];
    const float* w_ih  = (const float*)d_in[4];
    const float* w_hh  = (const float*)d_in[5];
    const float* b_ih  = (const float*)d_in[6];
    const float* b_hh  = (const float*)d_in[7];
    const float* fc_w  = (const float*)d_in[8];
    const float* fc_b  = (const float*)d_in[9];
    float* out = (float*)d_out;

    prep_kernel<<<(L_LAYERS * NB * 120 + 255) / 256, 256>>>(w_ih0, w_ih, w_hh, b_ih, b_hh);

    static int once = 0;
    if (!once) {
        cudaFuncSetAttribute(lstm_hmma_kernel,
                             cudaFuncAttributeMaxDynamicSharedMemorySize, SMEM_BYTES);
        once = 1;
    }
    lstm_hmma_kernel<<<NCTA, NTH, SMEM_BYTES>>>(x, h0, c0, fc_w, fc_b, out);
}

// round 9
// speedup vs baseline: 4.9071x; 1.2243x over previous
#include <cuda_runtime.h>
#include <cuda_fp16.h>

#define BTOT     65536
#define ROWS_CTA 128
#define NCTA     (BTOT / ROWS_CTA)   // 512
#define NTH      256                 // 8 warps = 4 pairs x 32 rows
#define NPAIR    4
#define L_LAYERS 6
#define KT       7                   // k16 tiles: [0..49 in][50..99 h][100 bias][101..111 pad]
#define ASTR     240                 // conflict-free stride (60r mod 32 distinct)
#define NB       208                 // padded gate columns (13 blocks of 16)

#define B_BYTES  (NB * ASTR)              // 49920
#define A_OFF    B_BYTES
#define APAIR    (32 * ASTR)              // 7680
#define FCW_OFF  (A_OFF + NPAIR * APAIR)  // 80640
#define SMEM_BYTES 80896

typedef unsigned u32;
typedef unsigned short u16;

__device__ __align__(16) char g_wB[L_LAYERS * B_BYTES]; // fp16 weights+bias, 240B rows
__device__ u16                g_ys[3ull * BTOT * 50];   // fp16 hidden outputs

static __device__ __forceinline__ u32 smem_u32(const void* p) {
    u32 a;
    asm("{ .reg .u64 t; cvta.to.shared.u64 t, %1; cvt.u32.u64 %0, t; }" : "=r"(a) : "l"(p));
    return a;
}
static __device__ __forceinline__ void ldsm4(u32 addr, u32* r) {
    asm volatile("ldmatrix.sync.aligned.m8n8.x4.shared.b16 {%0,%1,%2,%3}, [%4];"
                 : "=r"(r[0]), "=r"(r[1]), "=r"(r[2]), "=r"(r[3]) : "r"(addr));
}
static __device__ __forceinline__ void mma4(float* c, const u32* a, u32 b0, u32 b1) {
    asm("mma.sync.aligned.m16n8k16.row.col.f32.f16.f16.f32 "
        "{%0,%1,%2,%3},{%4,%5,%6,%7},{%8,%9},{%0,%1,%2,%3};"
        : "+f"(c[0]), "+f"(c[1]), "+f"(c[2]), "+f"(c[3])
        : "r"(a[0]), "r"(a[1]), "r"(a[2]), "r"(a[3]), "r"(b0), "r"(b1));
}
static __device__ __forceinline__ float rcpa(float x) {
    float r; asm("rcp.approx.f32 %0, %1;" : "=f"(r) : "f"(x)); return r;
}
#define BARP(id) asm volatile("bar.sync %0, 64;" :: "r"(id) : "memory")

// exact LSTM cell, 7 MUFU (5 EX2 + 2 RCP), shared-rcp c update, clamp only vs -inf NaN
static __device__ __forceinline__ float lstm_cell(float gi, float gf, float gg, float go,
                                                  float& cst) {
    float e1 = __expf(-gi);
    float ef = __expf(-gf);
    float e2 = __expf(-2.f * fmaxf(gg, -15.f));
    float a1 = 1.f + e1, af = 1.f + ef, a2 = 1.f + e2;
    float p12 = a1 * a2;
    float num = __fmaf_rn(cst, p12, (1.f - e2) * af);
    float cn = num * rcpa(p12 * af);
    cst = cn;
    float ec = __expf(-2.f * fmaxf(cn, -15.f));
    float eo = __expf(-go);
    return (1.f - ec) * rcpa((1.f + eo) * (1.f + ec));
}

// ---------------- prep: weights+bias -> fp16, shfl-free gate layout, 240B rows ----------------
// col n -> unit = 4*(n>>4) + ((n&7)>>1), gate = (n&1) + 2*((n>>3)&1); units >=50 zero pad.
__global__ void prep_kernel(const float* __restrict__ w_ih0, const float* __restrict__ w_ih,
                            const float* __restrict__ w_hh,  const float* __restrict__ b_ih,
                            const float* __restrict__ b_hh) {
    int idx = blockIdx.x * 256 + threadIdx.x;
    if (idx >= L_LAYERS * NB * 120) return;
    int k = idx % 120;
    int n = (idx / 120) % NB;
    int l = idx / (120 * NB);
    int u = 4 * (n >> 4) + ((n & 7) >> 1);
    int g = (n & 1) + 2 * ((n >> 3) & 1);
    float wv = 0.0f;
    if (u < 50) {
        int rt = g * 50 + u;
        if (k < 50)        wv = (l == 0) ? (k < 3 ? w_ih0[rt * 3 + k] : 0.0f)
                                         : w_ih[((size_t)(l - 1) * 200 + rt) * 50 + k];
        else if (k < 100)  wv = w_hh[((size_t)l * 200 + rt) * 50 + (k - 50)];
        else if (k == 100) wv = b_ih[l * 200 + rt] + b_hh[l * 200 + rt];
    }
    __half* base = (__half*)(g_wB + (size_t)l * B_BYTES);
    base[(size_t)n * 120 + k] = __float2half_rn(wv);
}

// one n16 tile: 5..7 ldsm + 28 mma + 4 cells, fully straight-line
#define J_TILE(J, JJ)                                                          \
  {                                                                            \
    float acc[16] = {0.f,0.f,0.f,0.f,0.f,0.f,0.f,0.f,                          \
                     0.f,0.f,0.f,0.f,0.f,0.f,0.f,0.f};                         \
    const u32 tb = bB4 + (J) * (16 * ASTR);                                    \
    _Pragma("unroll")                                                          \
    for (int kt = 0; kt < KT; ++kt) {                                          \
        u32 bh[4];                                                             \
        ldsm4(tb + kt * 32, bh);                                               \
        mma4(acc + 0,  afr[0][kt], bh[0], bh[1]);                              \
        mma4(acc + 4,  afr[0][kt], bh[2], bh[3]);                              \
        mma4(acc + 8,  afr[1][kt], bh[0], bh[1]);                              \
        mma4(acc + 12, afr[1][kt], bh[2], bh[3]);                              \
    }                                                                          \
    const int u_ = 4 * (J) + q;                                                \
    const bool ok_ = (u_ < 50);                                                \
    _Pragma("unroll")                                                          \
    for (int mt = 0; mt < 2; ++mt)                                             \
      _Pragma("unroll")                                                        \
      for (int h8 = 0; h8 < 2; ++h8) {                                         \
        float hv = lstm_cell(acc[mt*8 + h8*2 + 0], acc[mt*8 + h8*2 + 1],       \
                             acc[mt*8 + 4 + h8*2 + 0], acc[mt*8 + 4 + h8*2+1], \
                             cr[(JJ)*4 + mt*2 + h8]);                          \
        if (ok_) {                                                             \
            int row_ = r4 + 8*h8 + 16*mt;                                      \
            __half hh_ = __float2half_rn(hv);                                  \
            *(__half*)(Apair + row_*ASTR + (50 + u_)*2) = hh_;                 \
            g_ys[((size_t)t*BTOT + prb + row_)*50 + u_] = __half_as_ushort(hh_);\
        }                                                                      \
      }                                                                        \
  }

// ---------------- main ----------------
__global__ void __launch_bounds__(NTH, 2) lstm_hmma_kernel(
    const float* __restrict__ x,    const float* __restrict__ h0,
    const float* __restrict__ c0,   const float* __restrict__ fc_w,
    const float* __restrict__ fc_b, float* __restrict__ out)
{
    extern __shared__ char smem[];
    const u32 sbase = smem_u32(smem);
    const int tid = threadIdx.x, lane = tid & 31, w = tid >> 5;
    const int sub = w & 1, pid = w >> 1;
    const int q = lane & 3, r4 = lane >> 2;
    const int boff = blockIdx.x * ROWS_CTA;
    const int prb = boff + pid * 32;
    const int barid = 1 + pid;
    const int srow = lane;                 // staging row (0..31, both subs cover cols by parity)
    float* fcw_s = (float*)(smem + FCW_OFF);
    char* Apair = smem + A_OFF + pid * APAIR;
    char* Ar = Apair + srow * ASTR;

    for (int i = tid; i < (NPAIR * APAIR) / 16; i += NTH)
        ((float4*)(smem + A_OFF))[i] = make_float4(0.f, 0.f, 0.f, 0.f);
    if (tid < 50) fcw_s[tid] = fc_w[tid];
    __syncthreads();
    if (sub == 0)
        *(__half*)(Ar + 200) = __float2half(1.0f);     // bias col k=100

    const u32 aB  = sbase + A_OFF + pid * APAIR + (lane & 15) * ASTR + (lane >> 4) * 16;
    const u32 bB4 = sbase + (lane & 7) * ASTR + ((lane >> 3) & 1) * 16
                          + ((lane >> 4) & 1) * (8 * ASTR);

    float cr[28];
    u32 afr[2][KT][4];

    #pragma unroll 1
    for (int l = 0; l < L_LAYERS; ++l) {
        __syncthreads();
        const float4* ws = (const float4*)(g_wB + (size_t)l * B_BYTES);
        for (int i = tid; i < B_BYTES / 16; i += NTH) ((float4*)smem)[i] = __ldg(ws + i);
        __syncthreads();

        // h0 -> A cols 50..99 (fixed row per thread, col parity by sub)
        {
            const float2* hp = (const float2*)(h0 + ((size_t)l * BTOT + prb + srow) * 50);
            #pragma unroll
            for (int i = 0; i < 12; ++i) {
                int ci = 2 * i + sub;
                float2 v = hp[ci];
                *(__half2*)(Ar + 100 + 4 * ci) =
                    __halves2half2(__float2half_rn(v.x), __float2half_rn(v.y));
            }
            if (sub == 0) {
                float2 v = hp[24];
                *(__half2*)(Ar + 100 + 96) =
                    __halves2half2(__float2half_rn(v.x), __float2half_rn(v.y));
            }
        }
        // c0 -> regs (28 per thread; pad units get 0)
        {
            const float* cp = c0 + ((size_t)l * BTOT + prb) * 50;
            const int jbase = sub * 7;
            #pragma unroll
            for (int jj = 0; jj < 7; ++jj) {
                int u = 4 * (jbase + jj) + q;
                #pragma unroll
                for (int mt = 0; mt < 2; ++mt)
                    #pragma unroll
                    for (int h8 = 0; h8 < 2; ++h8) {
                        int row = r4 + 8 * h8 + 16 * mt;
                        cr[jj * 4 + mt * 2 + h8] = (u < 50) ? cp[(size_t)row * 50 + u] : 0.f;
                    }
            }
        }

        #pragma unroll 1
        for (int t = 0; t < 3; ++t) {
            // stage A input cols 0..49
            if (l == 0) {
                if (sub == 0) {
                    const float* xp = x + (size_t)(prb + srow) * 9 + t;
                    *(__half2*)(Ar) = __halves2half2(__float2half_rn(xp[0]),
                                                     __float2half_rn(xp[3]));
                    *(__half*)(Ar + 4) = __float2half_rn(xp[6]);
                }
            } else {
                const u32* yp = (const u32*)(g_ys + ((size_t)t * BTOT + prb + srow) * 50);
                #pragma unroll
                for (int i = 0; i < 12; ++i) {
                    int ci = 2 * i + sub;
                    *(u32*)(Ar + 4 * ci) = yp[ci];
                }
                if (sub == 0) *(u32*)(Ar + 96) = yp[24];
            }
            BARP(barid);                    // staging + partner's prev h-stores visible

            #pragma unroll
            for (int mt = 0; mt < 2; ++mt)
                #pragma unroll
                for (int kt = 0; kt < KT; ++kt)
                    ldsm4(aB + mt * (16 * ASTR) + kt * 32, afr[mt][kt]);
            BARP(barid);                    // A fully consumed; h-stores now safe

            if (sub == 0) {
                J_TILE(0, 0) J_TILE(1, 1) J_TILE(2, 2) J_TILE(3, 3)
                J_TILE(4, 4) J_TILE(5, 5) J_TILE(6, 6)
            } else {
                J_TILE(7, 0) J_TILE(8, 1) J_TILE(9, 2) J_TILE(10, 3)
                J_TILE(11, 4) J_TILE(12, 5)
            }
        }
    }

    // FC from final h (fp16, in A cols 50..99)
    __syncthreads();
    if (tid < 128) {
        int pr = tid >> 5, rr = tid & 31;
        const __half2* hh = (const __half2*)(smem + A_OFF + pr * APAIR + rr * ASTR + 100);
        float s = 0.f;
        #pragma unroll
        for (int i = 0; i < 25; ++i) {
            float2 hv = __half22float2(hh[i]);
            s = __fmaf_rn(hv.x, fcw_s[2 * i], s);
            s = __fmaf_rn(hv.y, fcw_s[2 * i + 1], s);
        }
        out[boff + tid] = s + fc_b[0];
    }
}

extern "C" void kernel_launch(void* const* d_in, const int* in_sizes, int n_in,
                              void* d_out, int out_size) {
    const float* x     = (const float*)d_in[0];
    const float* h0    = (const float*)d_in[1];
    const float* c0    = (const float*)d_in[2];
    const float* w_ih0 = (const float*)d_in[3];
    const float* w_ih  = (const float*)d_in[4];
    const float* w_hh  = (const float*)d_in[5];
    const float* b_ih  = (const float*)d_in[6];
    const float* b_hh  = (const float*)d_in[7];
    const float* fc_w  = (const float*)d_in[8];
    const float* fc_b  = (const float*)d_in[9];
    float* out = (float*)d_out;

    prep_kernel<<<(L_LAYERS * NB * 120 + 255) / 256, 256>>>(w_ih0, w_ih, w_hh, b_ih, b_hh);

    static int once = 0;
    if (!once) {
        cudaFuncSetAttribute(lstm_hmma_kernel,
                             cudaFuncAttributeMaxDynamicSharedMemorySize, SMEM_BYTES);
        once = 1;
    }
    lstm_hmma_kernel<<<NCTA, NTH, SMEM_BYTES>>>(x, h0, c0, fc_w, fc_b, out);
}